// round 6
// baseline (speedup 1.0000x reference)
#include <cuda_runtime.h>

#define HW   1048576
#define W0   1024
#define H0   1024
#define NIMG 20
#define B_   4
#define N_   5

// ---- scratch layout (floats) ----
#define OFF_HBOX  0u
#define OFF_GPL   20971520u
#define OFF_GPW   27934720u
#define OFF_ACC   34897920u
#define OFF_LSUM  36290560u
#define OFF_WSUM  36290580u
#define OFF_SCALE 36290600u
#define TOTAL_F   (36290624u)

// gp pyramid level offsets inside GPL / GPW regions (20 images per level)
#define L1OFF 0
#define L2OFF 5242880
#define L3OFF 6553600
#define L4OFF 6881280
// collapse accumulator offsets (4 images per level)
#define A1OFF 0
#define A2OFF 1048576
#define A3OFF 1310720
#define A4OFF 1376256

__device__ float g_buf[TOTAL_F];

// ---------------- fast math (avoid MUFU: rt=8/SMSP on B300) ----------------
__device__ __forceinline__ float fexp_(float x) {
    // exp(x) for x in ~[-40, 3]; FMA-only. 2^(x*log2e) with deg-5 poly on [-0.5,0.5].
    float y = x * 1.442695041f;
    float n = rintf(y);
    float f = y - n;
    float p = 1.33335581e-3f;
    p = fmaf(p, f, 9.61812910e-3f);
    p = fmaf(p, f, 5.55041087e-2f);
    p = fmaf(p, f, 2.40226507e-1f);
    p = fmaf(p, f, 6.93147180e-1f);
    p = fmaf(p, f, 1.0f);
    int e = (int)n;
    return __int_as_float(__float_as_int(p) + (e << 23));
}

__device__ __forceinline__ float frcp_(float a) {
    // reciprocal for positive normal a; bit-trick + 3 Newton steps (~1e-7 rel)
    float r = __int_as_float(0x7EF311C3 - __float_as_int(a));
    r = r * fmaf(-a, r, 2.0f);
    r = r * fmaf(-a, r, 2.0f);
    r = r * fmaf(-a, r, 2.0f);
    return r;
}

// ---------------- K0: zero accumulators ----------------
__global__ void k_zero() {
    if (threadIdx.x < 40) g_buf[OFF_LSUM + threadIdx.x] = 0.0f;  // LSUM[20]+WSUM[20]
}

// ---------------- K1: horizontal box sum of blown + per-image L sum ----------------
// one block per row. 128 threads, 8 px/thread sliding window, radius 30, zero pad.
// Global I/O via float4 (rows are 1024 floats, 16B-aligned).
__global__ void k_hbox(const float* __restrict__ L) {
    __shared__ float sb[1024];
    __shared__ float so[1024];
    __shared__ float red[4];
    int row = blockIdx.x;          // 0..20479
    int img = row >> 10;
    const float4* rp = (const float4*)(L + (size_t)row * W0);
    int t = threadIdx.x;

    float lsum = 0.f;
#pragma unroll
    for (int i = 0; i < 2; i++) {
        float4 v = rp[t + i * 128];
        lsum += v.x + v.y + v.z + v.w;
        int c = 4 * (t + i * 128);
        sb[c + 0] = fmaxf(v.x - 0.88f, 0.f);
        sb[c + 1] = fmaxf(v.y - 0.88f, 0.f);
        sb[c + 2] = fmaxf(v.z - 0.88f, 0.f);
        sb[c + 3] = fmaxf(v.w - 0.88f, 0.f);
    }
#pragma unroll
    for (int o = 16; o; o >>= 1) lsum += __shfl_down_sync(0xffffffffu, lsum, o);
    if ((t & 31) == 0) red[t >> 5] = lsum;
    __syncthreads();
    if (t == 0) atomicAdd(&g_buf[OFF_LSUM + img], red[0] + red[1] + red[2] + red[3]);

    int p0 = t * 8;
    int lo = p0 - 30; if (lo < 0) lo = 0;
    int hi = p0 + 30; if (hi > 1023) hi = 1023;
    float s = 0.f;
    for (int x = lo; x <= hi; x++) s += sb[x];
    so[p0] = s;
#pragma unroll
    for (int p = p0 + 1; p < p0 + 8; p++) {
        if (p + 30 <= 1023) s += sb[p + 30];
        if (p - 31 >= 0)    s -= sb[p - 31];
        so[p] = s;
    }
    __syncthreads();
    float4* op = (float4*)(g_buf + OFF_HBOX + (size_t)row * W0);
#pragma unroll
    for (int i = 0; i < 2; i++) {
        int c = 4 * (t + i * 128);
        op[t + i * 128] = make_float4(so[c], so[c + 1], so[c + 2], so[c + 3]);
    }
}

// ---------------- K2: vertical box (running sum) + quality + weights + wsum ----------------
// grid (W/256, 8 row-strips, B). Each thread walks 128 rows for all 5 exposures of batch b.
__global__ void k_qw(const float* __restrict__ Lin, float* __restrict__ wout) {
    const float* __restrict__ hbox = g_buf + OFF_HBOX;
    int x  = blockIdx.x * 256 + threadIdx.x;
    int b  = blockIdx.z;
    int y0 = blockIdx.y * 128;

    int off[5];
#pragma unroll
    for (int n = 0; n < 5; n++) off[n] = (b * 5 + n) * HW;

    float s[5], acc[5];
#pragma unroll
    for (int n = 0; n < 5; n++) { s[n] = 0.f; acc[n] = 0.f; }

    for (int r = y0 - 30; r < y0 + 30; r++) {
        if (r >= 0 && r < H0) {
            int ro = r * W0 + x;
#pragma unroll
            for (int n = 0; n < 5; n++) s[n] += hbox[off[n] + ro];
        }
    }

    for (int y = y0; y < y0 + 128; y++) {
        int ra = y + 30;
        if (ra < H0) {
            int ro = ra * W0 + x;
#pragma unroll
            for (int n = 0; n < 5; n++) s[n] += hbox[off[n] + ro];
        }
        int po = y * W0 + x;
        float q[5];
        float qs = 1e-6f;
#pragma unroll
        for (int n = 0; n < 5; n++) {
            float Lv  = Lin[off[n] + po];
            float tt  = fmaf(2.f, Lv, -1.f);
            float u   = fmaf(-tt, tt, 1.f);
            float base = u * u;
            float e1 = fexp_(15.f * (Lv - 0.88f));   // sat_pen = 1/(1+e1)
            float e2 = fexp_(-25.f * (Lv - 0.04f));  // dark_pen = 1/(1+e2)
            float den = (1.f + e1) * (1.f + e2);
            float bp = fexp_(s[n] * (-15.0f / 3721.0f));
            float qv = base * bp * frcp_(den);
            q[n] = fmaxf(qv, 0.02f);
            qs += q[n];
        }
        float inv = frcp_(qs);
#pragma unroll
        for (int n = 0; n < 5; n++) {
            float wv = q[n] * inv;
            wout[off[n] + po] = wv;
            acc[n] += wv;
        }
        int rb = y - 30;
        if (rb >= 0) {
            int ro = rb * W0 + x;
#pragma unroll
            for (int n = 0; n < 5; n++) s[n] -= hbox[off[n] + ro];
        }
    }

    __shared__ float sred[8][5];
#pragma unroll
    for (int n = 0; n < 5; n++) {
        float v = acc[n];
#pragma unroll
        for (int o = 16; o; o >>= 1) v += __shfl_down_sync(0xffffffffu, v, o);
        if ((threadIdx.x & 31) == 0) sred[threadIdx.x >> 5][n] = v;
    }
    __syncthreads();
    if (threadIdx.x < 5) {
        float t = 0.f;
#pragma unroll
        for (int wrp = 0; wrp < 8; wrp++) t += sred[wrp][threadIdx.x];
        atomicAdd(&g_buf[OFF_WSUM + b * 5 + threadIdx.x], t);
    }
}

// ---------------- K3: per-image exposure-compensation scale ----------------
__global__ void k_scale() {
    if (threadIdx.x != 0 || blockIdx.x != 0) return;
    const float invHW = 1.0f / (float)HW;
    for (int b = 0; b < 4; b++) {
        float num = 0.f, den = 1e-6f;
        float lm[5];
        for (int n = 0; n < 5; n++) {
            lm[n] = fmaxf(g_buf[OFF_LSUM + b * 5 + n] * invHW, 0.05f);
            float wm = g_buf[OFF_WSUM + b * 5 + n] * invHW;
            num += lm[n] * wm;
            den += wm;
        }
        float tgt = num / den;
        for (int n = 0; n < 5; n++) g_buf[OFF_SCALE + b * 5 + n] = tgt / lm[n];
    }
}

// ---------------- K4: fused 5x5-binomial-blur + 2x2 avgpool downsample ----------------
// separable 6-tap stride-2 kernel (1,5,10,10,5,1)/32 per axis, zero padding.
// block = 256 threads -> 32x8 outputs. Processes BOTH the L plane and the W plane:
// blockIdx.z in [0, 2*NIMG): z < NIMG -> L tensor, else W tensor.
// APPLY_SCALE (finest level only): L input is raw L, apply clip(L*scale).
template <bool APPLY_SCALE>
__global__ void k_down(const float* __restrict__ inL, const float* __restrict__ inW,
                       float* __restrict__ outL, float* __restrict__ outW,
                       int ih, int iw) {
    __shared__ float tile[20][68];
    __shared__ float hbuf[20][32];
    int z = blockIdx.z;
    bool isW = (z >= NIMG);
    int img = isW ? z - NIMG : z;
    const float* in = isW ? inW : inL;
    float* out = isW ? outW : outL;
    int ox0 = blockIdx.x * 32, oy0 = blockIdx.y * 8;
    int ow = iw >> 1;
    const float* ip = in + (size_t)img * ih * iw;
    float sc = (APPLY_SCALE && !isW) ? g_buf[OFF_SCALE + img] : 0.f;
    int gx0 = 2 * ox0 - 2, gy0 = 2 * oy0 - 2;

    for (int idx = threadIdx.x; idx < 20 * 68; idx += 256) {
        int r = idx / 68, c = idx - r * 68;
        int gy = gy0 + r, gx = gx0 + c;
        float v = 0.f;
        if (gy >= 0 && gy < ih && gx >= 0 && gx < iw) {
            v = ip[gy * iw + gx];
            if (APPLY_SCALE && !isW) v = fminf(fmaxf(v * sc, 0.f), 1.f);
        }
        tile[r][c] = v;
    }
    __syncthreads();
    for (int idx = threadIdx.x; idx < 20 * 32; idx += 256) {
        int r = idx >> 5, c = idx & 31;
        int bcol = 2 * c;
        hbuf[r][c] = 0.03125f * (tile[r][bcol] + tile[r][bcol + 5])
                   + 0.15625f * (tile[r][bcol + 1] + tile[r][bcol + 4])
                   + 0.3125f  * (tile[r][bcol + 2] + tile[r][bcol + 3]);
    }
    __syncthreads();
    int ty = threadIdx.x >> 5, tx = threadIdx.x & 31;
    int rr = 2 * ty;
    float v = 0.03125f * (hbuf[rr][tx] + hbuf[rr + 5][tx])
            + 0.15625f * (hbuf[rr + 1][tx] + hbuf[rr + 4][tx])
            + 0.3125f  * (hbuf[rr + 2][tx] + hbuf[rr + 3][tx]);
    out[(size_t)img * (ih >> 1) * ow + (oy0 + ty) * ow + (ox0 + tx)] = v;
}

// ---------------- bilinear-up helper (2x, half-pixel centers, clamped == jax renorm) ----
struct Bil { int i00, i01, i10, i11; float w00, w01, w10, w11; };
__device__ __forceinline__ Bil make_bil(int y, int x, int ih, int iw) {
    int y0 = (y - 1) >> 1, x0 = (x - 1) >> 1;
    float fy = (y & 1) ? 0.25f : 0.75f;
    float fx = (x & 1) ? 0.25f : 0.75f;
    int y0c = y0 < 0 ? 0 : y0;
    int y1c = (y0 + 1 > ih - 1) ? ih - 1 : y0 + 1;
    int x0c = x0 < 0 ? 0 : x0;
    int x1c = (x0 + 1 > iw - 1) ? iw - 1 : x0 + 1;
    Bil b;
    b.i00 = y0c * iw + x0c; b.i01 = y0c * iw + x1c;
    b.i10 = y1c * iw + x0c; b.i11 = y1c * iw + x1c;
    float gy = 1.f - fy, gx = 1.f - fx;
    b.w00 = gy * gx; b.w01 = gy * fx; b.w10 = fy * gx; b.w11 = fy * fx;
    return b;
}
__device__ __forceinline__ float bil(const float* __restrict__ p, const Bil& b) {
    return b.w00 * p[b.i00] + b.w01 * p[b.i01] + b.w10 * p[b.i10] + b.w11 * p[b.i11];
}

// ---------------- K5: coarsest-level blend (pure gaussian level) ----------------
__global__ void k_blend4() {
    const float* gpL4 = g_buf + OFF_GPL + L4OFF;
    const float* gpW4 = g_buf + OFF_GPW + L4OFF;
    float* acc4 = g_buf + OFF_ACC + A4OFF;
    int idx = blockIdx.x * 256 + threadIdx.x;
    if (idx >= 4 * 4096) return;
    int b = idx >> 12, p = idx & 4095;
    float wv[5], s = 1e-6f;
#pragma unroll
    for (int n = 0; n < 5; n++) { wv[n] = gpW4[(b * 5 + n) * 4096 + p]; s += wv[n]; }
    float inv = frcp_(s);
    float o = 0.f;
#pragma unroll
    for (int n = 0; n < 5; n++) o += wv[n] * inv * gpL4[(b * 5 + n) * 4096 + p];
    acc4[idx] = o;
}

// ---------------- K6: mid-level blend + collapse ----------------
// acc_out = up(acc_in) + sum_n wnorm_n * (gpL_l - up(gpL_{l+1}))
__global__ void k_blend(const float* __restrict__ Ll, const float* __restrict__ Ln,
                        const float* __restrict__ Wl, const float* __restrict__ accin,
                        float* __restrict__ accout, int oh, int ow) {
    int tx = threadIdx.x & 31, ty = threadIdx.x >> 5;
    int x = blockIdx.x * 32 + tx;
    int y = blockIdx.y * 8 + ty;
    int b = blockIdx.z;
    int ih = oh >> 1, iw = ow >> 1;
    int sz = oh * ow, isz = ih * iw;
    Bil bw = make_bil(y, x, ih, iw);
    int pix = y * ow + x;

    float wv[5], ssum = 1e-6f;
#pragma unroll
    for (int n = 0; n < 5; n++) { wv[n] = Wl[(b * 5 + n) * sz + pix]; ssum += wv[n]; }
    float inv = frcp_(ssum);

    float s = bil(accin + b * isz, bw);
#pragma unroll
    for (int n = 0; n < 5; n++) {
        float lv = Ll[(b * 5 + n) * sz + pix];
        float up = bil(Ln + (b * 5 + n) * isz, bw);
        s += wv[n] * inv * (lv - up);
    }
    accout[b * sz + pix] = s;
}

// ---------------- K7: finest-level blend + collapse + clip -> output ----------------
// gpL0 recomputed from input (clip(L*scale)); gpW0 = w buffer.
__global__ void k_blend0(const float* __restrict__ Lin, const float* __restrict__ Wl,
                         float* __restrict__ out) {
    const float* gpL1 = g_buf + OFF_GPL + L1OFF;
    const float* accin = g_buf + OFF_ACC + A1OFF;
    int tx = threadIdx.x & 31, ty = threadIdx.x >> 5;
    int x = blockIdx.x * 32 + tx;
    int y = blockIdx.y * 8 + ty;
    int b = blockIdx.z;
    const int ih = 512, iw = 512, isz = 262144;
    Bil bw = make_bil(y, x, ih, iw);
    int pix = y * W0 + x;

    float wv[5], ssum = 1e-6f;
#pragma unroll
    for (int n = 0; n < 5; n++) { wv[n] = Wl[(b * 5 + n) * HW + pix]; ssum += wv[n]; }
    float inv = frcp_(ssum);

    // acc1 is 512x512 per batch -> stride isz (R2 fix).
    float s = bil(accin + b * isz, bw);
#pragma unroll
    for (int n = 0; n < 5; n++) {
        int img = b * 5 + n;
        float lv = Lin[img * HW + pix] * g_buf[OFF_SCALE + img];
        lv = fminf(fmaxf(lv, 0.f), 1.f);
        float up = bil(gpL1 + img * isz, bw);
        s += wv[n] * inv * (lv - up);
    }
    out[b * HW + pix] = fminf(fmaxf(s, 0.f), 1.f);
}

// ---------------- host ----------------
extern "C" void kernel_launch(void* const* d_in, const int* in_sizes, int n_in,
                              void* d_out, int out_size) {
    const float* L = (const float*)d_in[0];
    float* out = (float*)d_out;

    float* base = nullptr;
    cudaGetSymbolAddress((void**)&base, g_buf);
    float* GPL = base + OFF_GPL;
    float* GPW = base + OFF_GPW;
    float* ACC = base + OFF_ACC;

    // output layout: [L_fused (4*HW)] ++ [w (20*HW)]
    float* wbuf = out + 4 * HW;

    k_zero<<<1, 64>>>();
    k_hbox<<<NIMG * H0, 128>>>(L);
    k_qw<<<dim3(4, 8, B_), 256>>>(L, wbuf);
    k_scale<<<1, 1>>>();

    k_down<true ><<<dim3(16, 64, 2 * NIMG), 256>>>(L,           wbuf,        GPL + L1OFF, GPW + L1OFF, 1024, 1024);
    k_down<false><<<dim3( 8, 32, 2 * NIMG), 256>>>(GPL + L1OFF, GPW + L1OFF, GPL + L2OFF, GPW + L2OFF,  512,  512);
    k_down<false><<<dim3( 4, 16, 2 * NIMG), 256>>>(GPL + L2OFF, GPW + L2OFF, GPL + L3OFF, GPW + L3OFF,  256,  256);
    k_down<false><<<dim3( 2,  8, 2 * NIMG), 256>>>(GPL + L3OFF, GPW + L3OFF, GPL + L4OFF, GPW + L4OFF,  128,  128);

    k_blend4<<<64, 256>>>();
    k_blend<<<dim3( 4, 16, B_), 256>>>(GPL + L3OFF, GPL + L4OFF, GPW + L3OFF,
                                       ACC + A4OFF, ACC + A3OFF, 128, 128);
    k_blend<<<dim3( 8, 32, B_), 256>>>(GPL + L2OFF, GPL + L3OFF, GPW + L2OFF,
                                       ACC + A3OFF, ACC + A2OFF, 256, 256);
    k_blend<<<dim3(16, 64, B_), 256>>>(GPL + L1OFF, GPL + L2OFF, GPW + L1OFF,
                                       ACC + A2OFF, ACC + A1OFF, 512, 512);
    k_blend0<<<dim3(32, 128, B_), 256>>>(L, wbuf, out);
}

// round 7
// speedup vs baseline: 1.2643x; 1.2643x over previous
#include <cuda_runtime.h>
#include <math.h>

#define HW   1048576
#define W0   1024
#define H0   1024
#define NIMG 20
#define B_   4
#define N_   5

// ---- scratch layout (floats) ----
#define OFF_HBOX  0u
#define OFF_GPL   20971520u
#define OFF_GPW   27934720u
#define OFF_ACC   34897920u
#define OFF_LSUM  36290560u
#define OFF_WSUM  36290580u
#define OFF_SCALE 36290600u
#define TOTAL_F   (36290624u)

// gp pyramid level offsets inside GPL / GPW regions (20 images per level)
#define L1OFF 0
#define L2OFF 5242880
#define L3OFF 6553600
#define L4OFF 6881280
// collapse accumulator offsets (4 images per level)
#define A1OFF 0
#define A2OFF 1048576
#define A3OFF 1310720
#define A4OFF 1376256

__device__ float g_buf[TOTAL_F];

// ---------------- fast math ----------------
__device__ __forceinline__ float frcp_(float a) {
    float r = __int_as_float(0x7EF311C3 - __float_as_int(a));
    r = r * fmaf(-a, r, 2.0f);
    r = r * fmaf(-a, r, 2.0f);
    r = r * fmaf(-a, r, 2.0f);
    return r;
}

// exp(x) for x in [-1.8, 0] (bloom argument range): pure-FMA Taylor at -0.9.
__device__ __forceinline__ float bloom_exp(float x) {
    float u = x + 0.9f;
    float p = 2.7557319e-6f;           // 1/9!
    p = fmaf(p, u, 2.4801587e-5f);     // 1/8!
    p = fmaf(p, u, 1.9841270e-4f);     // 1/7!
    p = fmaf(p, u, 1.3888889e-3f);     // 1/6!
    p = fmaf(p, u, 8.3333333e-3f);     // 1/5!
    p = fmaf(p, u, 4.1666667e-2f);     // 1/4!
    p = fmaf(p, u, 1.6666667e-1f);     // 1/3!
    p = fmaf(p, u, 0.5f);              // 1/2!
    p = fmaf(p, u, 1.0f);              // 1/1!
    p = fmaf(p, u, 1.0f);              // 1/0!
    return 0.40656966f * p;            // * e^-0.9
}

// exact L-quality (sans bloom): base_q * sat_pen * dark_pen — used to build LUT
__device__ __forceinline__ float qfun_(float L) {
    float t = fmaf(2.f, L, -1.f);
    float u = fmaf(-t, t, 1.f);
    float base = u * u;
    float sat  = 1.f / (1.f + expf(15.f * (L - 0.88f)));
    float dark = 1.f / (1.f + expf(-25.f * (L - 0.04f)));
    return base * sat * dark;
}

// ---------------- K0: zero accumulators ----------------
__global__ void k_zero() {
    if (threadIdx.x < 40) g_buf[OFF_LSUM + threadIdx.x] = 0.0f;  // LSUM[20]+WSUM[20]
}

// ---------------- K1: horizontal box sum of blown + per-image L sum ----------------
__global__ void k_hbox(const float* __restrict__ L) {
    __shared__ float sb[1024];
    __shared__ float so[1024];
    __shared__ float red[4];
    int row = blockIdx.x;          // 0..20479
    int img = row >> 10;
    const float4* rp = (const float4*)(L + (size_t)row * W0);
    int t = threadIdx.x;

    float lsum = 0.f;
#pragma unroll
    for (int i = 0; i < 2; i++) {
        float4 v = rp[t + i * 128];
        lsum += v.x + v.y + v.z + v.w;
        int c = 4 * (t + i * 128);
        sb[c + 0] = fmaxf(v.x - 0.88f, 0.f);
        sb[c + 1] = fmaxf(v.y - 0.88f, 0.f);
        sb[c + 2] = fmaxf(v.z - 0.88f, 0.f);
        sb[c + 3] = fmaxf(v.w - 0.88f, 0.f);
    }
#pragma unroll
    for (int o = 16; o; o >>= 1) lsum += __shfl_down_sync(0xffffffffu, lsum, o);
    if ((t & 31) == 0) red[t >> 5] = lsum;
    __syncthreads();
    if (t == 0) atomicAdd(&g_buf[OFF_LSUM + img], red[0] + red[1] + red[2] + red[3]);

    int p0 = t * 8;
    int lo = p0 - 30; if (lo < 0) lo = 0;
    int hi = p0 + 30; if (hi > 1023) hi = 1023;
    float s = 0.f;
    for (int x = lo; x <= hi; x++) s += sb[x];
    so[p0] = s;
#pragma unroll
    for (int p = p0 + 1; p < p0 + 8; p++) {
        if (p + 30 <= 1023) s += sb[p + 30];
        if (p - 31 >= 0)    s -= sb[p - 31];
        so[p] = s;
    }
    __syncthreads();
    float4* op = (float4*)(g_buf + OFF_HBOX + (size_t)row * W0);
#pragma unroll
    for (int i = 0; i < 2; i++) {
        int c = 4 * (t + i * 128);
        op[t + i * 128] = make_float4(so[c], so[c + 1], so[c + 2], so[c + 3]);
    }
}

// ---------------- K2: vertical box + quality (LUT) + weights + wsum ----------------
// grid (4, 16, B) = 256 blocks; 64-row strips; all loads hoisted per iteration.
__global__ void k_qw(const float* __restrict__ Lin, float* __restrict__ wout) {
    __shared__ float lut[2049];
    __shared__ float sred[8][5];
    const float* __restrict__ hbox = g_buf + OFF_HBOX;
    int tid = threadIdx.x;

    // build quality LUT (exact formula, 2049 entries over L in [0,1])
    for (int i = tid; i < 2049; i += 256) lut[i] = qfun_((float)i * (1.0f / 2048.0f));
    __syncthreads();

    int x  = blockIdx.x * 256 + tid;
    int b  = blockIdx.z;
    int y0 = blockIdx.y * 64;

    int off[5];
#pragma unroll
    for (int n = 0; n < 5; n++) off[n] = (b * 5 + n) * HW;

    float s[5], acc[5];
#pragma unroll
    for (int n = 0; n < 5; n++) { s[n] = 0.f; acc[n] = 0.f; }

    // warmup window [y0-30, y0+30)
    for (int r = y0 - 30; r < y0 + 30; r++) {
        if (r >= 0 && r < H0) {
            int ro = r * W0 + x;
#pragma unroll
            for (int n = 0; n < 5; n++) s[n] += hbox[off[n] + ro];
        }
    }

    const float cbl = -15.0f / 3721.0f;
    for (int y = y0; y < y0 + 64; y++) {
        // ---- issue ALL loads up front (15 independent LDG -> high MLP) ----
        int po = y * W0 + x;
        int ra = y + 30;  bool hasA = (ra < H0);  int rao = ra * W0 + x;
        int rb = y - 30;  bool hasB = (rb >= 0);  int rbo = rb * W0 + x;
        float li[5], hbA[5], hbB[5];
#pragma unroll
        for (int n = 0; n < 5; n++) li[n] = Lin[off[n] + po];
#pragma unroll
        for (int n = 0; n < 5; n++) hbA[n] = hasA ? hbox[off[n] + rao] : 0.f;
#pragma unroll
        for (int n = 0; n < 5; n++) hbB[n] = hasB ? hbox[off[n] + rbo] : 0.f;

        // ---- compute ----
        float q[5];
        float qs = 1e-6f;
#pragma unroll
        for (int n = 0; n < 5; n++) {
            s[n] += hbA[n];
            float a = li[n] * 2048.0f;
            int i = (int)a; i = i > 2047 ? 2047 : i;
            float f = a - (float)i;
            float l0 = lut[i], l1 = lut[i + 1];
            float qp = fmaf(f, l1 - l0, l0);
            float bp = bloom_exp(s[n] * cbl);
            float qv = qp * bp;
            q[n] = fmaxf(qv, 0.02f);
            qs += q[n];
        }
        float inv = frcp_(qs);
#pragma unroll
        for (int n = 0; n < 5; n++) {
            float wv = q[n] * inv;
            wout[off[n] + po] = wv;
            acc[n] += wv;
            s[n] -= hbB[n];
        }
    }

#pragma unroll
    for (int n = 0; n < 5; n++) {
        float v = acc[n];
#pragma unroll
        for (int o = 16; o; o >>= 1) v += __shfl_down_sync(0xffffffffu, v, o);
        if ((tid & 31) == 0) sred[tid >> 5][n] = v;
    }
    __syncthreads();
    if (tid < 5) {
        float t = 0.f;
#pragma unroll
        for (int wrp = 0; wrp < 8; wrp++) t += sred[wrp][tid];
        atomicAdd(&g_buf[OFF_WSUM + b * 5 + tid], t);
    }
}

// ---------------- K3: per-image exposure-compensation scale ----------------
__global__ void k_scale() {
    if (threadIdx.x != 0 || blockIdx.x != 0) return;
    const float invHW = 1.0f / (float)HW;
    for (int b = 0; b < 4; b++) {
        float num = 0.f, den = 1e-6f;
        float lm[5];
        for (int n = 0; n < 5; n++) {
            lm[n] = fmaxf(g_buf[OFF_LSUM + b * 5 + n] * invHW, 0.05f);
            float wm = g_buf[OFF_WSUM + b * 5 + n] * invHW;
            num += lm[n] * wm;
            den += wm;
        }
        float tgt = num / den;
        for (int n = 0; n < 5; n++) g_buf[OFF_SCALE + b * 5 + n] = tgt / lm[n];
    }
}

// ---------------- K4: fused 5x5-binomial-blur + 2x2 avgpool downsample ----------------
template <bool APPLY_SCALE>
__global__ void k_down(const float* __restrict__ inL, const float* __restrict__ inW,
                       float* __restrict__ outL, float* __restrict__ outW,
                       int ih, int iw) {
    __shared__ float tile[20][68];
    __shared__ float hbuf[20][32];
    int z = blockIdx.z;
    bool isW = (z >= NIMG);
    int img = isW ? z - NIMG : z;
    const float* in = isW ? inW : inL;
    float* out = isW ? outW : outL;
    int ox0 = blockIdx.x * 32, oy0 = blockIdx.y * 8;
    int ow = iw >> 1;
    const float* ip = in + (size_t)img * ih * iw;
    float sc = (APPLY_SCALE && !isW) ? g_buf[OFF_SCALE + img] : 0.f;
    int gx0 = 2 * ox0 - 2, gy0 = 2 * oy0 - 2;

    for (int idx = threadIdx.x; idx < 20 * 68; idx += 256) {
        int r = idx / 68, c = idx - r * 68;
        int gy = gy0 + r, gx = gx0 + c;
        float v = 0.f;
        if (gy >= 0 && gy < ih && gx >= 0 && gx < iw) {
            v = ip[gy * iw + gx];
            if (APPLY_SCALE && !isW) v = fminf(fmaxf(v * sc, 0.f), 1.f);
        }
        tile[r][c] = v;
    }
    __syncthreads();
    for (int idx = threadIdx.x; idx < 20 * 32; idx += 256) {
        int r = idx >> 5, c = idx & 31;
        int bcol = 2 * c;
        hbuf[r][c] = 0.03125f * (tile[r][bcol] + tile[r][bcol + 5])
                   + 0.15625f * (tile[r][bcol + 1] + tile[r][bcol + 4])
                   + 0.3125f  * (tile[r][bcol + 2] + tile[r][bcol + 3]);
    }
    __syncthreads();
    int ty = threadIdx.x >> 5, tx = threadIdx.x & 31;
    int rr = 2 * ty;
    float v = 0.03125f * (hbuf[rr][tx] + hbuf[rr + 5][tx])
            + 0.15625f * (hbuf[rr + 1][tx] + hbuf[rr + 4][tx])
            + 0.3125f  * (hbuf[rr + 2][tx] + hbuf[rr + 3][tx]);
    out[(size_t)img * (ih >> 1) * ow + (oy0 + ty) * ow + (ox0 + tx)] = v;
}

// ---------------- K5: coarsest-level blend (pure gaussian level) ----------------
__global__ void k_blend4() {
    const float* gpL4 = g_buf + OFF_GPL + L4OFF;
    const float* gpW4 = g_buf + OFF_GPW + L4OFF;
    float* acc4 = g_buf + OFF_ACC + A4OFF;
    int idx = blockIdx.x * 256 + threadIdx.x;
    if (idx >= 4 * 4096) return;
    int b = idx >> 12, p = idx & 4095;
    float wv[5], s = 1e-6f;
#pragma unroll
    for (int n = 0; n < 5; n++) { wv[n] = gpW4[(b * 5 + n) * 4096 + p]; s += wv[n]; }
    float inv = frcp_(s);
    float o = 0.f;
#pragma unroll
    for (int n = 0; n < 5; n++) o += wv[n] * inv * gpL4[(b * 5 + n) * 4096 + p];
    acc4[idx] = o;
}

// ---------------- smem-patch bilinear helpers ----------------
// Output tile 32x8 at (ox0,oy0); input (ih=oh/2, iw=ow/2). Patch: 6 rows x 18 cols,
// stored with row stride 20. Patch holds CLAMPED source values, so inner indices
// need no clamping (identical to index-clamped bilinear).
#define PATCH(ip, r, c) patch[(ip) * 120 + (r) * 20 + (c)]

// ---------------- K6: mid-level blend + collapse (smem bilinear) ----------------
__global__ void k_blend(const float* __restrict__ Ll, const float* __restrict__ Ln,
                        const float* __restrict__ Wl, const float* __restrict__ accin,
                        float* __restrict__ accout, int oh, int ow) {
    __shared__ float patch[6 * 120];  // 5 Ln images + 1 acc
    int tid = threadIdx.x;
    int tx = tid & 31, ty = tid >> 5;
    int ox0 = blockIdx.x * 32, oy0 = blockIdx.y * 8;
    int b = blockIdx.z;
    int ih = oh >> 1, iw = ow >> 1;
    int sz = oh * ow, isz = ih * iw;
    int py0 = (oy0 >> 1) - 1, px0 = (ox0 >> 1) - 1;

    for (int idx = tid; idx < 6 * 108; idx += 256) {
        int ip = idx / 108, rem = idx - ip * 108;
        int r = rem / 18, c = rem - r * 18;
        int sy = py0 + r; sy = sy < 0 ? 0 : (sy > ih - 1 ? ih - 1 : sy);
        int sx = px0 + c; sx = sx < 0 ? 0 : (sx > iw - 1 ? iw - 1 : sx);
        const float* src = (ip < 5) ? (Ln + (b * 5 + ip) * isz) : (accin + b * isz);
        PATCH(ip, r, c) = src[sy * iw + sx];
    }
    __syncthreads();

    int x = ox0 + tx, y = oy0 + ty;
    int pix = y * ow + x;
    int ly = ((y - 1) >> 1) - py0, lx = ((x - 1) >> 1) - px0;
    float fy = (y & 1) ? 0.25f : 0.75f;
    float fx = (x & 1) ? 0.25f : 0.75f;
    float gy = 1.f - fy, gx = 1.f - fx;
    float w00 = gy * gx, w01 = gy * fx, w10 = fy * gx, w11 = fy * fx;

    float wv[5], ssum = 1e-6f;
#pragma unroll
    for (int n = 0; n < 5; n++) { wv[n] = Wl[(b * 5 + n) * sz + pix]; ssum += wv[n]; }
    float inv = frcp_(ssum);

    float s = w00 * PATCH(5, ly, lx)     + w01 * PATCH(5, ly, lx + 1)
            + w10 * PATCH(5, ly + 1, lx) + w11 * PATCH(5, ly + 1, lx + 1);
#pragma unroll
    for (int n = 0; n < 5; n++) {
        float lv = Ll[(b * 5 + n) * sz + pix];
        float up = w00 * PATCH(n, ly, lx)     + w01 * PATCH(n, ly, lx + 1)
                 + w10 * PATCH(n, ly + 1, lx) + w11 * PATCH(n, ly + 1, lx + 1);
        s += wv[n] * inv * (lv - up);
    }
    accout[b * sz + pix] = s;
}

// ---------------- K7: finest-level blend + collapse + clip -> output ----------------
__global__ void k_blend0(const float* __restrict__ Lin, const float* __restrict__ Wl,
                         float* __restrict__ out) {
    __shared__ float patch[6 * 120];
    const float* gpL1 = g_buf + OFF_GPL + L1OFF;
    const float* accin = g_buf + OFF_ACC + A1OFF;
    int tid = threadIdx.x;
    int tx = tid & 31, ty = tid >> 5;
    int ox0 = blockIdx.x * 32, oy0 = blockIdx.y * 8;
    int b = blockIdx.z;
    const int ih = 512, iw = 512, isz = 262144;
    int py0 = (oy0 >> 1) - 1, px0 = (ox0 >> 1) - 1;

    for (int idx = tid; idx < 6 * 108; idx += 256) {
        int ip = idx / 108, rem = idx - ip * 108;
        int r = rem / 18, c = rem - r * 18;
        int sy = py0 + r; sy = sy < 0 ? 0 : (sy > ih - 1 ? ih - 1 : sy);
        int sx = px0 + c; sx = sx < 0 ? 0 : (sx > iw - 1 ? iw - 1 : sx);
        const float* src = (ip < 5) ? (gpL1 + (b * 5 + ip) * isz) : (accin + b * isz);
        PATCH(ip, r, c) = src[sy * iw + sx];
    }
    __syncthreads();

    int x = ox0 + tx, y = oy0 + ty;
    int pix = y * W0 + x;
    int ly = ((y - 1) >> 1) - py0, lx = ((x - 1) >> 1) - px0;
    float fy = (y & 1) ? 0.25f : 0.75f;
    float fx = (x & 1) ? 0.25f : 0.75f;
    float gy = 1.f - fy, gx = 1.f - fx;
    float w00 = gy * gx, w01 = gy * fx, w10 = fy * gx, w11 = fy * fx;

    float wv[5], ssum = 1e-6f;
#pragma unroll
    for (int n = 0; n < 5; n++) { wv[n] = Wl[(b * 5 + n) * HW + pix]; ssum += wv[n]; }
    float inv = frcp_(ssum);

    float s = w00 * PATCH(5, ly, lx)     + w01 * PATCH(5, ly, lx + 1)
            + w10 * PATCH(5, ly + 1, lx) + w11 * PATCH(5, ly + 1, lx + 1);
#pragma unroll
    for (int n = 0; n < 5; n++) {
        int img = b * 5 + n;
        float lv = Lin[img * HW + pix] * g_buf[OFF_SCALE + img];
        lv = fminf(fmaxf(lv, 0.f), 1.f);
        float up = w00 * PATCH(n, ly, lx)     + w01 * PATCH(n, ly, lx + 1)
                 + w10 * PATCH(n, ly + 1, lx) + w11 * PATCH(n, ly + 1, lx + 1);
        s += wv[n] * inv * (lv - up);
    }
    out[b * HW + pix] = fminf(fmaxf(s, 0.f), 1.f);
}

// ---------------- host ----------------
extern "C" void kernel_launch(void* const* d_in, const int* in_sizes, int n_in,
                              void* d_out, int out_size) {
    const float* L = (const float*)d_in[0];
    float* out = (float*)d_out;

    float* base = nullptr;
    cudaGetSymbolAddress((void**)&base, g_buf);
    float* GPL = base + OFF_GPL;
    float* GPW = base + OFF_GPW;
    float* ACC = base + OFF_ACC;

    // output layout: [L_fused (4*HW)] ++ [w (20*HW)]
    float* wbuf = out + 4 * HW;

    k_zero<<<1, 64>>>();
    k_hbox<<<NIMG * H0, 128>>>(L);
    k_qw<<<dim3(4, 16, B_), 256>>>(L, wbuf);
    k_scale<<<1, 1>>>();

    k_down<true ><<<dim3(16, 64, 2 * NIMG), 256>>>(L,           wbuf,        GPL + L1OFF, GPW + L1OFF, 1024, 1024);
    k_down<false><<<dim3( 8, 32, 2 * NIMG), 256>>>(GPL + L1OFF, GPW + L1OFF, GPL + L2OFF, GPW + L2OFF,  512,  512);
    k_down<false><<<dim3( 4, 16, 2 * NIMG), 256>>>(GPL + L2OFF, GPW + L2OFF, GPL + L3OFF, GPW + L3OFF,  256,  256);
    k_down<false><<<dim3( 2,  8, 2 * NIMG), 256>>>(GPL + L3OFF, GPW + L3OFF, GPL + L4OFF, GPW + L4OFF,  128,  128);

    k_blend4<<<64, 256>>>();
    k_blend<<<dim3( 4, 16, B_), 256>>>(GPL + L3OFF, GPL + L4OFF, GPW + L3OFF,
                                       ACC + A4OFF, ACC + A3OFF, 128, 128);
    k_blend<<<dim3( 8, 32, B_), 256>>>(GPL + L2OFF, GPL + L3OFF, GPW + L2OFF,
                                       ACC + A3OFF, ACC + A2OFF, 256, 256);
    k_blend<<<dim3(16, 64, B_), 256>>>(GPL + L1OFF, GPL + L2OFF, GPW + L1OFF,
                                       ACC + A2OFF, ACC + A1OFF, 512, 512);
    k_blend0<<<dim3(32, 128, B_), 256>>>(L, wbuf, out);
}

// round 9
// speedup vs baseline: 1.2643x; 1.0000x over previous
#include <cuda_runtime.h>
#include <math.h>

#define HW   1048576
#define W0   1024
#define H0   1024
#define NIMG 20
#define B_   4
#define N_   5

// ---- scratch layout (floats) ----
#define OFF_HBOX  0u
#define OFF_GPL   20971520u
#define OFF_GPW   27934720u
#define OFF_ACC   34897920u
#define OFF_LSUM  36290560u
#define OFF_WSUM  36290580u
#define OFF_SCALE 36290600u
#define TOTAL_F   (36290624u)

// gp pyramid level offsets inside GPL / GPW regions (20 images per level)
#define L1OFF 0
#define L2OFF 5242880
#define L3OFF 6553600
#define L4OFF 6881280
// collapse accumulator offsets (4 images per level)
#define A1OFF 0
#define A2OFF 1048576
#define A3OFF 1310720
#define A4OFF 1376256

__device__ float g_buf[TOTAL_F];

// ---------------- fast math ----------------
__device__ __forceinline__ float frcp_(float a) {
    float r = __int_as_float(0x7EF311C3 - __float_as_int(a));
    r = r * fmaf(-a, r, 2.0f);
    r = r * fmaf(-a, r, 2.0f);
    r = r * fmaf(-a, r, 2.0f);
    return r;
}

// exp(x) for x in [-1.8, 0] (bloom argument range): pure-FMA Taylor at -0.9.
__device__ __forceinline__ float bloom_exp(float x) {
    float u = x + 0.9f;
    float p = 2.7557319e-6f;           // 1/9!
    p = fmaf(p, u, 2.4801587e-5f);     // 1/8!
    p = fmaf(p, u, 1.9841270e-4f);     // 1/7!
    p = fmaf(p, u, 1.3888889e-3f);     // 1/6!
    p = fmaf(p, u, 8.3333333e-3f);     // 1/5!
    p = fmaf(p, u, 4.1666667e-2f);     // 1/4!
    p = fmaf(p, u, 1.6666667e-1f);     // 1/3!
    p = fmaf(p, u, 0.5f);              // 1/2!
    p = fmaf(p, u, 1.0f);              // 1/1!
    p = fmaf(p, u, 1.0f);              // 1/0!
    return 0.40656966f * p;            // * e^-0.9
}

// exact L-quality (sans bloom): base_q * sat_pen * dark_pen — used to build LUT
__device__ __forceinline__ float qfun_(float L) {
    float t = fmaf(2.f, L, -1.f);
    float u = fmaf(-t, t, 1.f);
    float base = u * u;
    float sat  = 1.f / (1.f + expf(15.f * (L - 0.88f)));
    float dark = 1.f / (1.f + expf(-25.f * (L - 0.04f)));
    return base * sat * dark;
}

// ---------------- K0: zero accumulators ----------------
__global__ void k_zero() {
    if (threadIdx.x < 40) g_buf[OFF_LSUM + threadIdx.x] = 0.0f;  // LSUM[20]+WSUM[20]
}

// ---------------- spacer: aligns the ncu capture slot (-s 5 -c 1 => our idx 3)
// so that k_qw is the profiled kernel. Harmless: zeroes 4 unused scale slots.
__global__ void k_spacer() {
    if (threadIdx.x < 4) g_buf[OFF_SCALE + 20 + threadIdx.x] = 0.0f;
}

// ---------------- K1: horizontal box sum of blown + per-image L sum ----------------
__global__ void k_hbox(const float* __restrict__ L) {
    __shared__ float sb[1024];
    __shared__ float so[1024];
    __shared__ float red[4];
    int row = blockIdx.x;          // 0..20479
    int img = row >> 10;
    const float4* rp = (const float4*)(L + (size_t)row * W0);
    int t = threadIdx.x;

    float lsum = 0.f;
#pragma unroll
    for (int i = 0; i < 2; i++) {
        float4 v = rp[t + i * 128];
        lsum += v.x + v.y + v.z + v.w;
        int c = 4 * (t + i * 128);
        sb[c + 0] = fmaxf(v.x - 0.88f, 0.f);
        sb[c + 1] = fmaxf(v.y - 0.88f, 0.f);
        sb[c + 2] = fmaxf(v.z - 0.88f, 0.f);
        sb[c + 3] = fmaxf(v.w - 0.88f, 0.f);
    }
#pragma unroll
    for (int o = 16; o; o >>= 1) lsum += __shfl_down_sync(0xffffffffu, lsum, o);
    if ((t & 31) == 0) red[t >> 5] = lsum;
    __syncthreads();
    if (t == 0) atomicAdd(&g_buf[OFF_LSUM + img], red[0] + red[1] + red[2] + red[3]);

    int p0 = t * 8;
    int lo = p0 - 30; if (lo < 0) lo = 0;
    int hi = p0 + 30; if (hi > 1023) hi = 1023;
    float s = 0.f;
    for (int x = lo; x <= hi; x++) s += sb[x];
    so[p0] = s;
#pragma unroll
    for (int p = p0 + 1; p < p0 + 8; p++) {
        if (p + 30 <= 1023) s += sb[p + 30];
        if (p - 31 >= 0)    s -= sb[p - 31];
        so[p] = s;
    }
    __syncthreads();
    float4* op = (float4*)(g_buf + OFF_HBOX + (size_t)row * W0);
#pragma unroll
    for (int i = 0; i < 2; i++) {
        int c = 4 * (t + i * 128);
        op[t + i * 128] = make_float4(so[c], so[c + 1], so[c + 2], so[c + 3]);
    }
}

// ---------------- K2: vertical box + quality (LUT) + weights + wsum ----------------
// grid (4, 16, B) = 256 blocks; 64-row strips; all loads hoisted per iteration.
__global__ void k_qw(const float* __restrict__ Lin, float* __restrict__ wout) {
    __shared__ float lut[2049];
    __shared__ float sred[8][5];
    const float* __restrict__ hbox = g_buf + OFF_HBOX;
    int tid = threadIdx.x;

    // build quality LUT (exact formula, 2049 entries over L in [0,1])
    for (int i = tid; i < 2049; i += 256) lut[i] = qfun_((float)i * (1.0f / 2048.0f));
    __syncthreads();

    int x  = blockIdx.x * 256 + tid;
    int b  = blockIdx.z;
    int y0 = blockIdx.y * 64;

    int off[5];
#pragma unroll
    for (int n = 0; n < 5; n++) off[n] = (b * 5 + n) * HW;

    float s[5], acc[5];
#pragma unroll
    for (int n = 0; n < 5; n++) { s[n] = 0.f; acc[n] = 0.f; }

    // warmup window [y0-30, y0+30)
    for (int r = y0 - 30; r < y0 + 30; r++) {
        if (r >= 0 && r < H0) {
            int ro = r * W0 + x;
#pragma unroll
            for (int n = 0; n < 5; n++) s[n] += hbox[off[n] + ro];
        }
    }

    const float cbl = -15.0f / 3721.0f;
    for (int y = y0; y < y0 + 64; y++) {
        // ---- issue ALL loads up front (15 independent LDG -> high MLP) ----
        int po = y * W0 + x;
        int ra = y + 30;  bool hasA = (ra < H0);  int rao = ra * W0 + x;
        int rb = y - 30;  bool hasB = (rb >= 0);  int rbo = rb * W0 + x;
        float li[5], hbA[5], hbB[5];
#pragma unroll
        for (int n = 0; n < 5; n++) li[n] = Lin[off[n] + po];
#pragma unroll
        for (int n = 0; n < 5; n++) hbA[n] = hasA ? hbox[off[n] + rao] : 0.f;
#pragma unroll
        for (int n = 0; n < 5; n++) hbB[n] = hasB ? hbox[off[n] + rbo] : 0.f;

        // ---- compute ----
        float q[5];
        float qs = 1e-6f;
#pragma unroll
        for (int n = 0; n < 5; n++) {
            s[n] += hbA[n];
            float a = li[n] * 2048.0f;
            int i = (int)a; i = i > 2047 ? 2047 : i;
            float f = a - (float)i;
            float l0 = lut[i], l1 = lut[i + 1];
            float qp = fmaf(f, l1 - l0, l0);
            float bp = bloom_exp(s[n] * cbl);
            float qv = qp * bp;
            q[n] = fmaxf(qv, 0.02f);
            qs += q[n];
        }
        float inv = frcp_(qs);
#pragma unroll
        for (int n = 0; n < 5; n++) {
            float wv = q[n] * inv;
            wout[off[n] + po] = wv;
            acc[n] += wv;
            s[n] -= hbB[n];
        }
    }

#pragma unroll
    for (int n = 0; n < 5; n++) {
        float v = acc[n];
#pragma unroll
        for (int o = 16; o; o >>= 1) v += __shfl_down_sync(0xffffffffu, v, o);
        if ((tid & 31) == 0) sred[tid >> 5][n] = v;
    }
    __syncthreads();
    if (tid < 5) {
        float t = 0.f;
#pragma unroll
        for (int wrp = 0; wrp < 8; wrp++) t += sred[wrp][tid];
        atomicAdd(&g_buf[OFF_WSUM + b * 5 + tid], t);
    }
}

// ---------------- K3: per-image exposure-compensation scale ----------------
__global__ void k_scale() {
    if (threadIdx.x != 0 || blockIdx.x != 0) return;
    const float invHW = 1.0f / (float)HW;
    for (int b = 0; b < 4; b++) {
        float num = 0.f, den = 1e-6f;
        float lm[5];
        for (int n = 0; n < 5; n++) {
            lm[n] = fmaxf(g_buf[OFF_LSUM + b * 5 + n] * invHW, 0.05f);
            float wm = g_buf[OFF_WSUM + b * 5 + n] * invHW;
            num += lm[n] * wm;
            den += wm;
        }
        float tgt = num / den;
        for (int n = 0; n < 5; n++) g_buf[OFF_SCALE + b * 5 + n] = tgt / lm[n];
    }
}

// ---------------- K4: fused 5x5-binomial-blur + 2x2 avgpool downsample ----------------
template <bool APPLY_SCALE>
__global__ void k_down(const float* __restrict__ inL, const float* __restrict__ inW,
                       float* __restrict__ outL, float* __restrict__ outW,
                       int ih, int iw) {
    __shared__ float tile[20][68];
    __shared__ float hbuf[20][32];
    int z = blockIdx.z;
    bool isW = (z >= NIMG);
    int img = isW ? z - NIMG : z;
    const float* in = isW ? inW : inL;
    float* out = isW ? outW : outL;
    int ox0 = blockIdx.x * 32, oy0 = blockIdx.y * 8;
    int ow = iw >> 1;
    const float* ip = in + (size_t)img * ih * iw;
    float sc = (APPLY_SCALE && !isW) ? g_buf[OFF_SCALE + img] : 0.f;
    int gx0 = 2 * ox0 - 2, gy0 = 2 * oy0 - 2;

    for (int idx = threadIdx.x; idx < 20 * 68; idx += 256) {
        int r = idx / 68, c = idx - r * 68;
        int gy = gy0 + r, gx = gx0 + c;
        float v = 0.f;
        if (gy >= 0 && gy < ih && gx >= 0 && gx < iw) {
            v = ip[gy * iw + gx];
            if (APPLY_SCALE && !isW) v = fminf(fmaxf(v * sc, 0.f), 1.f);
        }
        tile[r][c] = v;
    }
    __syncthreads();
    for (int idx = threadIdx.x; idx < 20 * 32; idx += 256) {
        int r = idx >> 5, c = idx & 31;
        int bcol = 2 * c;
        hbuf[r][c] = 0.03125f * (tile[r][bcol] + tile[r][bcol + 5])
                   + 0.15625f * (tile[r][bcol + 1] + tile[r][bcol + 4])
                   + 0.3125f  * (tile[r][bcol + 2] + tile[r][bcol + 3]);
    }
    __syncthreads();
    int ty = threadIdx.x >> 5, tx = threadIdx.x & 31;
    int rr = 2 * ty;
    float v = 0.03125f * (hbuf[rr][tx] + hbuf[rr + 5][tx])
            + 0.15625f * (hbuf[rr + 1][tx] + hbuf[rr + 4][tx])
            + 0.3125f  * (hbuf[rr + 2][tx] + hbuf[rr + 3][tx]);
    out[(size_t)img * (ih >> 1) * ow + (oy0 + ty) * ow + (ox0 + tx)] = v;
}

// ---------------- K5: coarsest-level blend (pure gaussian level) ----------------
__global__ void k_blend4() {
    const float* gpL4 = g_buf + OFF_GPL + L4OFF;
    const float* gpW4 = g_buf + OFF_GPW + L4OFF;
    float* acc4 = g_buf + OFF_ACC + A4OFF;
    int idx = blockIdx.x * 256 + threadIdx.x;
    if (idx >= 4 * 4096) return;
    int b = idx >> 12, p = idx & 4095;
    float wv[5], s = 1e-6f;
#pragma unroll
    for (int n = 0; n < 5; n++) { wv[n] = gpW4[(b * 5 + n) * 4096 + p]; s += wv[n]; }
    float inv = frcp_(s);
    float o = 0.f;
#pragma unroll
    for (int n = 0; n < 5; n++) o += wv[n] * inv * gpL4[(b * 5 + n) * 4096 + p];
    acc4[idx] = o;
}

// ---------------- smem-patch bilinear helpers ----------------
#define PATCH(ip, r, c) patch[(ip) * 120 + (r) * 20 + (c)]

// ---------------- K6: mid-level blend + collapse (smem bilinear) ----------------
__global__ void k_blend(const float* __restrict__ Ll, const float* __restrict__ Ln,
                        const float* __restrict__ Wl, const float* __restrict__ accin,
                        float* __restrict__ accout, int oh, int ow) {
    __shared__ float patch[6 * 120];  // 5 Ln images + 1 acc
    int tid = threadIdx.x;
    int tx = tid & 31, ty = tid >> 5;
    int ox0 = blockIdx.x * 32, oy0 = blockIdx.y * 8;
    int b = blockIdx.z;
    int ih = oh >> 1, iw = ow >> 1;
    int sz = oh * ow, isz = ih * iw;
    int py0 = (oy0 >> 1) - 1, px0 = (ox0 >> 1) - 1;

    for (int idx = tid; idx < 6 * 108; idx += 256) {
        int ip = idx / 108, rem = idx - ip * 108;
        int r = rem / 18, c = rem - r * 18;
        int sy = py0 + r; sy = sy < 0 ? 0 : (sy > ih - 1 ? ih - 1 : sy);
        int sx = px0 + c; sx = sx < 0 ? 0 : (sx > iw - 1 ? iw - 1 : sx);
        const float* src = (ip < 5) ? (Ln + (b * 5 + ip) * isz) : (accin + b * isz);
        PATCH(ip, r, c) = src[sy * iw + sx];
    }
    __syncthreads();

    int x = ox0 + tx, y = oy0 + ty;
    int pix = y * ow + x;
    int ly = ((y - 1) >> 1) - py0, lx = ((x - 1) >> 1) - px0;
    float fy = (y & 1) ? 0.25f : 0.75f;
    float fx = (x & 1) ? 0.25f : 0.75f;
    float gy = 1.f - fy, gx = 1.f - fx;
    float w00 = gy * gx, w01 = gy * fx, w10 = fy * gx, w11 = fy * fx;

    float wv[5], ssum = 1e-6f;
#pragma unroll
    for (int n = 0; n < 5; n++) { wv[n] = Wl[(b * 5 + n) * sz + pix]; ssum += wv[n]; }
    float inv = frcp_(ssum);

    float s = w00 * PATCH(5, ly, lx)     + w01 * PATCH(5, ly, lx + 1)
            + w10 * PATCH(5, ly + 1, lx) + w11 * PATCH(5, ly + 1, lx + 1);
#pragma unroll
    for (int n = 0; n < 5; n++) {
        float lv = Ll[(b * 5 + n) * sz + pix];
        float up = w00 * PATCH(n, ly, lx)     + w01 * PATCH(n, ly, lx + 1)
                 + w10 * PATCH(n, ly + 1, lx) + w11 * PATCH(n, ly + 1, lx + 1);
        s += wv[n] * inv * (lv - up);
    }
    accout[b * sz + pix] = s;
}

// ---------------- K7: finest-level blend + collapse + clip -> output ----------------
__global__ void k_blend0(const float* __restrict__ Lin, const float* __restrict__ Wl,
                         float* __restrict__ out) {
    __shared__ float patch[6 * 120];
    const float* gpL1 = g_buf + OFF_GPL + L1OFF;
    const float* accin = g_buf + OFF_ACC + A1OFF;
    int tid = threadIdx.x;
    int tx = tid & 31, ty = tid >> 5;
    int ox0 = blockIdx.x * 32, oy0 = blockIdx.y * 8;
    int b = blockIdx.z;
    const int ih = 512, iw = 512, isz = 262144;
    int py0 = (oy0 >> 1) - 1, px0 = (ox0 >> 1) - 1;

    for (int idx = tid; idx < 6 * 108; idx += 256) {
        int ip = idx / 108, rem = idx - ip * 108;
        int r = rem / 18, c = rem - r * 18;
        int sy = py0 + r; sy = sy < 0 ? 0 : (sy > ih - 1 ? ih - 1 : sy);
        int sx = px0 + c; sx = sx < 0 ? 0 : (sx > iw - 1 ? iw - 1 : sx);
        const float* src = (ip < 5) ? (gpL1 + (b * 5 + ip) * isz) : (accin + b * isz);
        PATCH(ip, r, c) = src[sy * iw + sx];
    }
    __syncthreads();

    int x = ox0 + tx, y = oy0 + ty;
    int pix = y * W0 + x;
    int ly = ((y - 1) >> 1) - py0, lx = ((x - 1) >> 1) - px0;
    float fy = (y & 1) ? 0.25f : 0.75f;
    float fx = (x & 1) ? 0.25f : 0.75f;
    float gy = 1.f - fy, gx = 1.f - fx;
    float w00 = gy * gx, w01 = gy * fx, w10 = fy * gx, w11 = fy * fx;

    float wv[5], ssum = 1e-6f;
#pragma unroll
    for (int n = 0; n < 5; n++) { wv[n] = Wl[(b * 5 + n) * HW + pix]; ssum += wv[n]; }
    float inv = frcp_(ssum);

    float s = w00 * PATCH(5, ly, lx)     + w01 * PATCH(5, ly, lx + 1)
            + w10 * PATCH(5, ly + 1, lx) + w11 * PATCH(5, ly + 1, lx + 1);
#pragma unroll
    for (int n = 0; n < 5; n++) {
        int img = b * 5 + n;
        float lv = Lin[img * HW + pix] * g_buf[OFF_SCALE + img];
        lv = fminf(fmaxf(lv, 0.f), 1.f);
        float up = w00 * PATCH(n, ly, lx)     + w01 * PATCH(n, ly, lx + 1)
                 + w10 * PATCH(n, ly + 1, lx) + w11 * PATCH(n, ly + 1, lx + 1);
        s += wv[n] * inv * (lv - up);
    }
    out[b * HW + pix] = fminf(fmaxf(s, 0.f), 1.f);
}

// ---------------- host ----------------
extern "C" void kernel_launch(void* const* d_in, const int* in_sizes, int n_in,
                              void* d_out, int out_size) {
    const float* L = (const float*)d_in[0];
    float* out = (float*)d_out;

    float* base = nullptr;
    cudaGetSymbolAddress((void**)&base, g_buf);
    float* GPL = base + OFF_GPL;
    float* GPW = base + OFF_GPW;
    float* ACC = base + OFF_ACC;

    // output layout: [L_fused (4*HW)] ++ [w (20*HW)]
    float* wbuf = out + 4 * HW;

    k_zero<<<1, 64>>>();            // idx 0
    k_hbox<<<NIMG * H0, 128>>>(L);  // idx 1
    k_spacer<<<1, 32>>>();          // idx 2  (slot-shifter: capture lands on idx 3)
    k_qw<<<dim3(4, 16, B_), 256>>>(L, wbuf);  // idx 3  <-- ncu capture slot
    k_scale<<<1, 1>>>();

    k_down<true ><<<dim3(16, 64, 2 * NIMG), 256>>>(L,           wbuf,        GPL + L1OFF, GPW + L1OFF, 1024, 1024);
    k_down<false><<<dim3( 8, 32, 2 * NIMG), 256>>>(GPL + L1OFF, GPW + L1OFF, GPL + L2OFF, GPW + L2OFF,  512,  512);
    k_down<false><<<dim3( 4, 16, 2 * NIMG), 256>>>(GPL + L2OFF, GPW + L2OFF, GPL + L3OFF, GPW + L3OFF,  256,  256);
    k_down<false><<<dim3( 2,  8, 2 * NIMG), 256>>>(GPL + L3OFF, GPW + L3OFF, GPL + L4OFF, GPW + L4OFF,  128,  128);

    k_blend4<<<64, 256>>>();
    k_blend<<<dim3( 4, 16, B_), 256>>>(GPL + L3OFF, GPL + L4OFF, GPW + L3OFF,
                                       ACC + A4OFF, ACC + A3OFF, 128, 128);
    k_blend<<<dim3( 8, 32, B_), 256>>>(GPL + L2OFF, GPL + L3OFF, GPW + L2OFF,
                                       ACC + A3OFF, ACC + A2OFF, 256, 256);
    k_blend<<<dim3(16, 64, B_), 256>>>(GPL + L1OFF, GPL + L2OFF, GPW + L1OFF,
                                       ACC + A2OFF, ACC + A1OFF, 512, 512);
    k_blend0<<<dim3(32, 128, B_), 256>>>(L, wbuf, out);
}

// round 10
// speedup vs baseline: 1.3832x; 1.0940x over previous
#include <cuda_runtime.h>
#include <math.h>

#define HW   1048576
#define W0   1024
#define H0   1024
#define NIMG 20
#define B_   4
#define N_   5

// ---- scratch layout (floats) ----
#define OFF_HBOX  0u
#define OFF_GPL   20971520u
#define OFF_GPW   27934720u
#define OFF_ACC   34897920u
#define OFF_LSUM  36290560u
#define OFF_WSUM  36290580u
#define OFF_SCALE 36290600u
#define TOTAL_F   (36290624u)

// gp pyramid level offsets inside GPL / GPW regions (20 images per level)
#define L1OFF 0
#define L2OFF 5242880
#define L3OFF 6553600
#define L4OFF 6881280
// collapse accumulator offsets (4 images per level)
#define A1OFF 0
#define A2OFF 1048576
#define A3OFF 1310720
#define A4OFF 1376256

__device__ float g_buf[TOTAL_F];

// ---------------- fast math ----------------
__device__ __forceinline__ float frcp_(float a) {
    float r = __int_as_float(0x7EF311C3 - __float_as_int(a));
    r = r * fmaf(-a, r, 2.0f);
    r = r * fmaf(-a, r, 2.0f);
    r = r * fmaf(-a, r, 2.0f);
    return r;
}

// exp(x) for x in [-1.8, 0] (bloom argument range): pure-FMA Taylor at -0.9.
__device__ __forceinline__ float bloom_exp(float x) {
    float u = x + 0.9f;
    float p = 2.7557319e-6f;           // 1/9!
    p = fmaf(p, u, 2.4801587e-5f);     // 1/8!
    p = fmaf(p, u, 1.9841270e-4f);     // 1/7!
    p = fmaf(p, u, 1.3888889e-3f);     // 1/6!
    p = fmaf(p, u, 8.3333333e-3f);     // 1/5!
    p = fmaf(p, u, 4.1666667e-2f);     // 1/4!
    p = fmaf(p, u, 1.6666667e-1f);     // 1/3!
    p = fmaf(p, u, 0.5f);              // 1/2!
    p = fmaf(p, u, 1.0f);              // 1/1!
    p = fmaf(p, u, 1.0f);              // 1/0!
    return 0.40656966f * p;            // * e^-0.9
}

// exact L-quality (sans bloom): base_q * sat_pen * dark_pen — used to build LUT
__device__ __forceinline__ float qfun_(float L) {
    float t = fmaf(2.f, L, -1.f);
    float u = fmaf(-t, t, 1.f);
    float base = u * u;
    float sat  = 1.f / (1.f + expf(15.f * (L - 0.88f)));
    float dark = 1.f / (1.f + expf(-25.f * (L - 0.04f)));
    return base * sat * dark;
}

// per-(b,n) exposure-compensation scale from finished LSUM/WSUM reductions.
// Uniform-address loads: broadcast + L1-cached; ~10 LDG + 30 flops.
__device__ __forceinline__ float scale_for(int b, int n) {
    const float invHW = 1.0f / (float)HW;
    float num = 0.f, den = 1e-6f, lmn = 1.f;
#pragma unroll
    for (int k = 0; k < 5; k++) {
        float lm = fmaxf(g_buf[OFF_LSUM + b * 5 + k] * invHW, 0.05f);
        float wm = g_buf[OFF_WSUM + b * 5 + k] * invHW;
        num += lm * wm;
        den += wm;
        if (k == n) lmn = lm;
    }
    return (num / den) / lmn;
}

// ---------------- K0: zero accumulators ----------------
__global__ void k_zero() {
    if (threadIdx.x < 40) g_buf[OFF_LSUM + threadIdx.x] = 0.0f;  // LSUM[20]+WSUM[20]
}

// ---------------- K1: horizontal box sum of blown + per-image L sum ----------------
__global__ void k_hbox(const float* __restrict__ L) {
    __shared__ float sb[1024];
    __shared__ float so[1024];
    __shared__ float red[4];
    int row = blockIdx.x;          // 0..20479
    int img = row >> 10;
    const float4* rp = (const float4*)(L + (size_t)row * W0);
    int t = threadIdx.x;

    float lsum = 0.f;
#pragma unroll
    for (int i = 0; i < 2; i++) {
        float4 v = rp[t + i * 128];
        lsum += v.x + v.y + v.z + v.w;
        int c = 4 * (t + i * 128);
        sb[c + 0] = fmaxf(v.x - 0.88f, 0.f);
        sb[c + 1] = fmaxf(v.y - 0.88f, 0.f);
        sb[c + 2] = fmaxf(v.z - 0.88f, 0.f);
        sb[c + 3] = fmaxf(v.w - 0.88f, 0.f);
    }
#pragma unroll
    for (int o = 16; o; o >>= 1) lsum += __shfl_down_sync(0xffffffffu, lsum, o);
    if ((t & 31) == 0) red[t >> 5] = lsum;
    __syncthreads();
    if (t == 0) atomicAdd(&g_buf[OFF_LSUM + img], red[0] + red[1] + red[2] + red[3]);

    int p0 = t * 8;
    int lo = p0 - 30; if (lo < 0) lo = 0;
    int hi = p0 + 30; if (hi > 1023) hi = 1023;
    float s = 0.f;
    for (int x = lo; x <= hi; x++) s += sb[x];
    so[p0] = s;
#pragma unroll
    for (int p = p0 + 1; p < p0 + 8; p++) {
        if (p + 30 <= 1023) s += sb[p + 30];
        if (p - 31 >= 0)    s -= sb[p - 31];
        so[p] = s;
    }
    __syncthreads();
    float4* op = (float4*)(g_buf + OFF_HBOX + (size_t)row * W0);
#pragma unroll
    for (int i = 0; i < 2; i++) {
        int c = 4 * (t + i * 128);
        op[t + i * 128] = make_float4(so[c], so[c + 1], so[c + 2], so[c + 3]);
    }
}

// ---------------- K2: vertical box + quality (LUT) + weights + wsum ----------------
// grid (4, 32, B) = 512 blocks; 32-row strips (R10: was 64 — occ 21.5% -> ~43%).
__global__ void k_qw(const float* __restrict__ Lin, float* __restrict__ wout) {
    __shared__ float lut[2049];
    __shared__ float sred[8][5];
    const float* __restrict__ hbox = g_buf + OFF_HBOX;
    int tid = threadIdx.x;

    // build quality LUT (exact formula, 2049 entries over L in [0,1])
    for (int i = tid; i < 2049; i += 256) lut[i] = qfun_((float)i * (1.0f / 2048.0f));
    __syncthreads();

    int x  = blockIdx.x * 256 + tid;
    int b  = blockIdx.z;
    int y0 = blockIdx.y * 32;

    int off[5];
#pragma unroll
    for (int n = 0; n < 5; n++) off[n] = (b * 5 + n) * HW;

    float s[5], acc[5];
#pragma unroll
    for (int n = 0; n < 5; n++) { s[n] = 0.f; acc[n] = 0.f; }

    // warmup window [y0-30, y0+30)
    for (int r = y0 - 30; r < y0 + 30; r++) {
        if (r >= 0 && r < H0) {
            int ro = r * W0 + x;
#pragma unroll
            for (int n = 0; n < 5; n++) s[n] += hbox[off[n] + ro];
        }
    }

    const float cbl = -15.0f / 3721.0f;
    for (int y = y0; y < y0 + 32; y++) {
        // ---- issue ALL loads up front (15 independent LDG -> high MLP) ----
        int po = y * W0 + x;
        int ra = y + 30;  bool hasA = (ra < H0);  int rao = ra * W0 + x;
        int rb = y - 30;  bool hasB = (rb >= 0);  int rbo = rb * W0 + x;
        float li[5], hbA[5], hbB[5];
#pragma unroll
        for (int n = 0; n < 5; n++) li[n] = Lin[off[n] + po];
#pragma unroll
        for (int n = 0; n < 5; n++) hbA[n] = hasA ? hbox[off[n] + rao] : 0.f;
#pragma unroll
        for (int n = 0; n < 5; n++) hbB[n] = hasB ? hbox[off[n] + rbo] : 0.f;

        // ---- compute ----
        float q[5];
        float qs = 1e-6f;
#pragma unroll
        for (int n = 0; n < 5; n++) {
            s[n] += hbA[n];
            float a = li[n] * 2048.0f;
            int i = (int)a; i = i > 2047 ? 2047 : i;
            float f = a - (float)i;
            float l0 = lut[i], l1 = lut[i + 1];
            float qp = fmaf(f, l1 - l0, l0);
            float bp = bloom_exp(s[n] * cbl);
            float qv = qp * bp;
            q[n] = fmaxf(qv, 0.02f);
            qs += q[n];
        }
        float inv = frcp_(qs);
#pragma unroll
        for (int n = 0; n < 5; n++) {
            float wv = q[n] * inv;
            wout[off[n] + po] = wv;
            acc[n] += wv;
            s[n] -= hbB[n];
        }
    }

#pragma unroll
    for (int n = 0; n < 5; n++) {
        float v = acc[n];
#pragma unroll
        for (int o = 16; o; o >>= 1) v += __shfl_down_sync(0xffffffffu, v, o);
        if ((tid & 31) == 0) sred[tid >> 5][n] = v;
    }
    __syncthreads();
    if (tid < 5) {
        float t = 0.f;
#pragma unroll
        for (int wrp = 0; wrp < 8; wrp++) t += sred[wrp][tid];
        atomicAdd(&g_buf[OFF_WSUM + b * 5 + tid], t);
    }
}

// ---------------- K4: fused 5x5-binomial-blur + 2x2 avgpool downsample ----------------
// APPLY_SCALE (finest level, L half): scale computed inline per block (no k_scale).
template <bool APPLY_SCALE>
__global__ void k_down(const float* __restrict__ inL, const float* __restrict__ inW,
                       float* __restrict__ outL, float* __restrict__ outW,
                       int ih, int iw) {
    __shared__ float tile[20][68];
    __shared__ float hbuf[20][32];
    __shared__ float s_scale;
    int z = blockIdx.z;
    bool isW = (z >= NIMG);
    int img = isW ? z - NIMG : z;
    const float* in = isW ? inW : inL;
    float* out = isW ? outW : outL;
    int ox0 = blockIdx.x * 32, oy0 = blockIdx.y * 8;
    int ow = iw >> 1;
    const float* ip = in + (size_t)img * ih * iw;

    if (APPLY_SCALE) {
        if (threadIdx.x == 0)
            s_scale = isW ? 1.0f : scale_for(img / 5, img % 5);
        __syncthreads();
    }
    float sc = APPLY_SCALE ? s_scale : 0.f;

    int gx0 = 2 * ox0 - 2, gy0 = 2 * oy0 - 2;

    for (int idx = threadIdx.x; idx < 20 * 68; idx += 256) {
        int r = idx / 68, c = idx - r * 68;
        int gy = gy0 + r, gx = gx0 + c;
        float v = 0.f;
        if (gy >= 0 && gy < ih && gx >= 0 && gx < iw) {
            v = ip[gy * iw + gx];
            if (APPLY_SCALE && !isW) v = fminf(fmaxf(v * sc, 0.f), 1.f);
        }
        tile[r][c] = v;
    }
    __syncthreads();
    for (int idx = threadIdx.x; idx < 20 * 32; idx += 256) {
        int r = idx >> 5, c = idx & 31;
        int bcol = 2 * c;
        hbuf[r][c] = 0.03125f * (tile[r][bcol] + tile[r][bcol + 5])
                   + 0.15625f * (tile[r][bcol + 1] + tile[r][bcol + 4])
                   + 0.3125f  * (tile[r][bcol + 2] + tile[r][bcol + 3]);
    }
    __syncthreads();
    int ty = threadIdx.x >> 5, tx = threadIdx.x & 31;
    int rr = 2 * ty;
    float v = 0.03125f * (hbuf[rr][tx] + hbuf[rr + 5][tx])
            + 0.15625f * (hbuf[rr + 1][tx] + hbuf[rr + 4][tx])
            + 0.3125f  * (hbuf[rr + 2][tx] + hbuf[rr + 3][tx]);
    out[(size_t)img * (ih >> 1) * ow + (oy0 + ty) * ow + (ox0 + tx)] = v;
}

// ---------------- K5: coarsest-level blend (pure gaussian level) ----------------
__global__ void k_blend4() {
    const float* gpL4 = g_buf + OFF_GPL + L4OFF;
    const float* gpW4 = g_buf + OFF_GPW + L4OFF;
    float* acc4 = g_buf + OFF_ACC + A4OFF;
    int idx = blockIdx.x * 256 + threadIdx.x;
    if (idx >= 4 * 4096) return;
    int b = idx >> 12, p = idx & 4095;
    float wv[5], s = 1e-6f;
#pragma unroll
    for (int n = 0; n < 5; n++) { wv[n] = gpW4[(b * 5 + n) * 4096 + p]; s += wv[n]; }
    float inv = frcp_(s);
    float o = 0.f;
#pragma unroll
    for (int n = 0; n < 5; n++) o += wv[n] * inv * gpL4[(b * 5 + n) * 4096 + p];
    acc4[idx] = o;
}

// ---------------- smem-patch bilinear helpers ----------------
#define PATCH(ip, r, c) patch[(ip) * 120 + (r) * 20 + (c)]

// ---------------- K6: mid-level blend + collapse (smem bilinear) ----------------
__global__ void k_blend(const float* __restrict__ Ll, const float* __restrict__ Ln,
                        const float* __restrict__ Wl, const float* __restrict__ accin,
                        float* __restrict__ accout, int oh, int ow) {
    __shared__ float patch[6 * 120];  // 5 Ln images + 1 acc
    int tid = threadIdx.x;
    int tx = tid & 31, ty = tid >> 5;
    int ox0 = blockIdx.x * 32, oy0 = blockIdx.y * 8;
    int b = blockIdx.z;
    int ih = oh >> 1, iw = ow >> 1;
    int sz = oh * ow, isz = ih * iw;
    int py0 = (oy0 >> 1) - 1, px0 = (ox0 >> 1) - 1;

    for (int idx = tid; idx < 6 * 108; idx += 256) {
        int ip = idx / 108, rem = idx - ip * 108;
        int r = rem / 18, c = rem - r * 18;
        int sy = py0 + r; sy = sy < 0 ? 0 : (sy > ih - 1 ? ih - 1 : sy);
        int sx = px0 + c; sx = sx < 0 ? 0 : (sx > iw - 1 ? iw - 1 : sx);
        const float* src = (ip < 5) ? (Ln + (b * 5 + ip) * isz) : (accin + b * isz);
        PATCH(ip, r, c) = src[sy * iw + sx];
    }
    __syncthreads();

    int x = ox0 + tx, y = oy0 + ty;
    int pix = y * ow + x;
    int ly = ((y - 1) >> 1) - py0, lx = ((x - 1) >> 1) - px0;
    float fy = (y & 1) ? 0.25f : 0.75f;
    float fx = (x & 1) ? 0.25f : 0.75f;
    float gy = 1.f - fy, gx = 1.f - fx;
    float w00 = gy * gx, w01 = gy * fx, w10 = fy * gx, w11 = fy * fx;

    float wv[5], ssum = 1e-6f;
#pragma unroll
    for (int n = 0; n < 5; n++) { wv[n] = Wl[(b * 5 + n) * sz + pix]; ssum += wv[n]; }
    float inv = frcp_(ssum);

    float s = w00 * PATCH(5, ly, lx)     + w01 * PATCH(5, ly, lx + 1)
            + w10 * PATCH(5, ly + 1, lx) + w11 * PATCH(5, ly + 1, lx + 1);
#pragma unroll
    for (int n = 0; n < 5; n++) {
        float lv = Ll[(b * 5 + n) * sz + pix];
        float up = w00 * PATCH(n, ly, lx)     + w01 * PATCH(n, ly, lx + 1)
                 + w10 * PATCH(n, ly + 1, lx) + w11 * PATCH(n, ly + 1, lx + 1);
        s += wv[n] * inv * (lv - up);
    }
    accout[b * sz + pix] = s;
}

// ---------------- K7: finest-level blend + collapse + clip -> output ----------------
__global__ void k_blend0(const float* __restrict__ Lin, const float* __restrict__ Wl,
                         float* __restrict__ out) {
    __shared__ float patch[6 * 120];
    __shared__ float s_sc[5];
    const float* gpL1 = g_buf + OFF_GPL + L1OFF;
    const float* accin = g_buf + OFF_ACC + A1OFF;
    int tid = threadIdx.x;
    int tx = tid & 31, ty = tid >> 5;
    int ox0 = blockIdx.x * 32, oy0 = blockIdx.y * 8;
    int b = blockIdx.z;
    const int ih = 512, iw = 512, isz = 262144;
    int py0 = (oy0 >> 1) - 1, px0 = (ox0 >> 1) - 1;

    if (tid < 5) s_sc[tid] = scale_for(b, tid);

    for (int idx = tid; idx < 6 * 108; idx += 256) {
        int ip = idx / 108, rem = idx - ip * 108;
        int r = rem / 18, c = rem - r * 18;
        int sy = py0 + r; sy = sy < 0 ? 0 : (sy > ih - 1 ? ih - 1 : sy);
        int sx = px0 + c; sx = sx < 0 ? 0 : (sx > iw - 1 ? iw - 1 : sx);
        const float* src = (ip < 5) ? (gpL1 + (b * 5 + ip) * isz) : (accin + b * isz);
        PATCH(ip, r, c) = src[sy * iw + sx];
    }
    __syncthreads();

    int x = ox0 + tx, y = oy0 + ty;
    int pix = y * W0 + x;
    int ly = ((y - 1) >> 1) - py0, lx = ((x - 1) >> 1) - px0;
    float fy = (y & 1) ? 0.25f : 0.75f;
    float fx = (x & 1) ? 0.25f : 0.75f;
    float gy = 1.f - fy, gx = 1.f - fx;
    float w00 = gy * gx, w01 = gy * fx, w10 = fy * gx, w11 = fy * fx;

    float wv[5], ssum = 1e-6f;
#pragma unroll
    for (int n = 0; n < 5; n++) { wv[n] = Wl[(b * 5 + n) * HW + pix]; ssum += wv[n]; }
    float inv = frcp_(ssum);

    float s = w00 * PATCH(5, ly, lx)     + w01 * PATCH(5, ly, lx + 1)
            + w10 * PATCH(5, ly + 1, lx) + w11 * PATCH(5, ly + 1, lx + 1);
#pragma unroll
    for (int n = 0; n < 5; n++) {
        int img = b * 5 + n;
        float lv = Lin[img * HW + pix] * s_sc[n];
        lv = fminf(fmaxf(lv, 0.f), 1.f);
        float up = w00 * PATCH(n, ly, lx)     + w01 * PATCH(n, ly, lx + 1)
                 + w10 * PATCH(n, ly + 1, lx) + w11 * PATCH(n, ly + 1, lx + 1);
        s += wv[n] * inv * (lv - up);
    }
    out[b * HW + pix] = fminf(fmaxf(s, 0.f), 1.f);
}

// ---------------- host ----------------
extern "C" void kernel_launch(void* const* d_in, const int* in_sizes, int n_in,
                              void* d_out, int out_size) {
    const float* L = (const float*)d_in[0];
    float* out = (float*)d_out;

    float* base = nullptr;
    cudaGetSymbolAddress((void**)&base, g_buf);
    float* GPL = base + OFF_GPL;
    float* GPW = base + OFF_GPW;
    float* ACC = base + OFF_ACC;

    // output layout: [L_fused (4*HW)] ++ [w (20*HW)]
    float* wbuf = out + 4 * HW;

    k_zero<<<1, 64>>>();                       // idx 0
    k_hbox<<<NIMG * H0, 128>>>(L);             // idx 1
    k_qw<<<dim3(4, 32, B_), 256>>>(L, wbuf);   // idx 2
    // idx 3 <-- ncu capture slot: level-1 downsample (scale computed inline)
    k_down<true ><<<dim3(16, 64, 2 * NIMG), 256>>>(L,           wbuf,        GPL + L1OFF, GPW + L1OFF, 1024, 1024);
    k_down<false><<<dim3( 8, 32, 2 * NIMG), 256>>>(GPL + L1OFF, GPW + L1OFF, GPL + L2OFF, GPW + L2OFF,  512,  512);
    k_down<false><<<dim3( 4, 16, 2 * NIMG), 256>>>(GPL + L2OFF, GPW + L2OFF, GPL + L3OFF, GPW + L3OFF,  256,  256);
    k_down<false><<<dim3( 2,  8, 2 * NIMG), 256>>>(GPL + L3OFF, GPW + L3OFF, GPL + L4OFF, GPW + L4OFF,  128,  128);

    k_blend4<<<64, 256>>>();
    k_blend<<<dim3( 4, 16, B_), 256>>>(GPL + L3OFF, GPL + L4OFF, GPW + L3OFF,
                                       ACC + A4OFF, ACC + A3OFF, 128, 128);
    k_blend<<<dim3( 8, 32, B_), 256>>>(GPL + L2OFF, GPL + L3OFF, GPW + L2OFF,
                                       ACC + A3OFF, ACC + A2OFF, 256, 256);
    k_blend<<<dim3(16, 64, B_), 256>>>(GPL + L1OFF, GPL + L2OFF, GPW + L1OFF,
                                       ACC + A2OFF, ACC + A1OFF, 512, 512);
    k_blend0<<<dim3(32, 128, B_), 256>>>(L, wbuf, out);
}

// round 11
// speedup vs baseline: 1.6088x; 1.1631x over previous
#include <cuda_runtime.h>
#include <math.h>

#define HW   1048576
#define W0   1024
#define H0   1024
#define NIMG 20
#define B_   4
#define N_   5

// ---- scratch layout (floats) ----
#define OFF_HBOX  0u
#define OFF_GPL   20971520u
#define OFF_GPW   27934720u
#define OFF_ACC   34897920u
#define OFF_LSUM  36290560u
#define OFF_WSUM  36290580u
#define OFF_SCALE 36290600u
#define TOTAL_F   (36290624u)

// gp pyramid level offsets inside GPL / GPW regions (20 images per level)
#define L1OFF 0
#define L2OFF 5242880
#define L3OFF 6553600
#define L4OFF 6881280
// collapse accumulator offsets (4 images per level)
#define A1OFF 0
#define A2OFF 1048576
#define A3OFF 1310720
#define A4OFF 1376256

__device__ float g_buf[TOTAL_F];

// ---------------- fast math ----------------
__device__ __forceinline__ float frcp_(float a) {
    float r = __int_as_float(0x7EF311C3 - __float_as_int(a));
    r = r * fmaf(-a, r, 2.0f);
    r = r * fmaf(-a, r, 2.0f);
    r = r * fmaf(-a, r, 2.0f);
    return r;
}

// exp(x) for x in [-1.8, 0] (bloom argument range): pure-FMA Taylor at -0.9.
__device__ __forceinline__ float bloom_exp(float x) {
    float u = x + 0.9f;
    float p = 2.7557319e-6f;           // 1/9!
    p = fmaf(p, u, 2.4801587e-5f);     // 1/8!
    p = fmaf(p, u, 1.9841270e-4f);     // 1/7!
    p = fmaf(p, u, 1.3888889e-3f);     // 1/6!
    p = fmaf(p, u, 8.3333333e-3f);     // 1/5!
    p = fmaf(p, u, 4.1666667e-2f);     // 1/4!
    p = fmaf(p, u, 1.6666667e-1f);     // 1/3!
    p = fmaf(p, u, 0.5f);              // 1/2!
    p = fmaf(p, u, 1.0f);              // 1/1!
    p = fmaf(p, u, 1.0f);              // 1/0!
    return 0.40656966f * p;            // * e^-0.9
}

// exact L-quality (sans bloom): base_q * sat_pen * dark_pen — used to build LUT
__device__ __forceinline__ float qfun_(float L) {
    float t = fmaf(2.f, L, -1.f);
    float u = fmaf(-t, t, 1.f);
    float base = u * u;
    float sat  = 1.f / (1.f + expf(15.f * (L - 0.88f)));
    float dark = 1.f / (1.f + expf(-25.f * (L - 0.04f)));
    return base * sat * dark;
}

// per-(b,n) exposure-compensation scale from finished LSUM/WSUM reductions.
__device__ __forceinline__ float scale_for(int b, int n) {
    const float invHW = 1.0f / (float)HW;
    float num = 0.f, den = 1e-6f, lmn = 1.f;
#pragma unroll
    for (int k = 0; k < 5; k++) {
        float lm = fmaxf(g_buf[OFF_LSUM + b * 5 + k] * invHW, 0.05f);
        float wm = g_buf[OFF_WSUM + b * 5 + k] * invHW;
        num += lm * wm;
        den += wm;
        if (k == n) lmn = lm;
    }
    return (num / den) / lmn;
}

// ---------------- K0: zero accumulators ----------------
__global__ void k_zero() {
    if (threadIdx.x < 40) g_buf[OFF_LSUM + threadIdx.x] = 0.0f;  // LSUM[20]+WSUM[20]
}

// ---------------- K1: horizontal box sum of blown + per-image L sum ----------------
__global__ void k_hbox(const float* __restrict__ L) {
    __shared__ float sb[1024];
    __shared__ float so[1024];
    __shared__ float red[4];
    int row = blockIdx.x;          // 0..20479
    int img = row >> 10;
    const float4* rp = (const float4*)(L + (size_t)row * W0);
    int t = threadIdx.x;

    float lsum = 0.f;
#pragma unroll
    for (int i = 0; i < 2; i++) {
        float4 v = rp[t + i * 128];
        lsum += v.x + v.y + v.z + v.w;
        int c = 4 * (t + i * 128);
        sb[c + 0] = fmaxf(v.x - 0.88f, 0.f);
        sb[c + 1] = fmaxf(v.y - 0.88f, 0.f);
        sb[c + 2] = fmaxf(v.z - 0.88f, 0.f);
        sb[c + 3] = fmaxf(v.w - 0.88f, 0.f);
    }
#pragma unroll
    for (int o = 16; o; o >>= 1) lsum += __shfl_down_sync(0xffffffffu, lsum, o);
    if ((t & 31) == 0) red[t >> 5] = lsum;
    __syncthreads();
    if (t == 0) atomicAdd(&g_buf[OFF_LSUM + img], red[0] + red[1] + red[2] + red[3]);

    int p0 = t * 8;
    int lo = p0 - 30; if (lo < 0) lo = 0;
    int hi = p0 + 30; if (hi > 1023) hi = 1023;
    float s = 0.f;
    for (int x = lo; x <= hi; x++) s += sb[x];
    so[p0] = s;
#pragma unroll
    for (int p = p0 + 1; p < p0 + 8; p++) {
        if (p + 30 <= 1023) s += sb[p + 30];
        if (p - 31 >= 0)    s -= sb[p - 31];
        so[p] = s;
    }
    __syncthreads();
    float4* op = (float4*)(g_buf + OFF_HBOX + (size_t)row * W0);
#pragma unroll
    for (int i = 0; i < 2; i++) {
        int c = 4 * (t + i * 128);
        op[t + i * 128] = make_float4(so[c], so[c + 1], so[c + 2], so[c + 3]);
    }
}

// ---------------- K2: vertical box + quality (LUT) + weights + wsum ----------------
// grid (4, 32, B) = 512 blocks; 32-row strips.
__global__ void k_qw(const float* __restrict__ Lin, float* __restrict__ wout) {
    __shared__ float lut[2049];
    __shared__ float sred[8][5];
    const float* __restrict__ hbox = g_buf + OFF_HBOX;
    int tid = threadIdx.x;

    for (int i = tid; i < 2049; i += 256) lut[i] = qfun_((float)i * (1.0f / 2048.0f));
    __syncthreads();

    int x  = blockIdx.x * 256 + tid;
    int b  = blockIdx.z;
    int y0 = blockIdx.y * 32;

    int off[5];
#pragma unroll
    for (int n = 0; n < 5; n++) off[n] = (b * 5 + n) * HW;

    float s[5], acc[5];
#pragma unroll
    for (int n = 0; n < 5; n++) { s[n] = 0.f; acc[n] = 0.f; }

    for (int r = y0 - 30; r < y0 + 30; r++) {
        if (r >= 0 && r < H0) {
            int ro = r * W0 + x;
#pragma unroll
            for (int n = 0; n < 5; n++) s[n] += hbox[off[n] + ro];
        }
    }

    const float cbl = -15.0f / 3721.0f;
    for (int y = y0; y < y0 + 32; y++) {
        int po = y * W0 + x;
        int ra = y + 30;  bool hasA = (ra < H0);  int rao = ra * W0 + x;
        int rb = y - 30;  bool hasB = (rb >= 0);  int rbo = rb * W0 + x;
        float li[5], hbA[5], hbB[5];
#pragma unroll
        for (int n = 0; n < 5; n++) li[n] = Lin[off[n] + po];
#pragma unroll
        for (int n = 0; n < 5; n++) hbA[n] = hasA ? hbox[off[n] + rao] : 0.f;
#pragma unroll
        for (int n = 0; n < 5; n++) hbB[n] = hasB ? hbox[off[n] + rbo] : 0.f;

        float q[5];
        float qs = 1e-6f;
#pragma unroll
        for (int n = 0; n < 5; n++) {
            s[n] += hbA[n];
            float a = li[n] * 2048.0f;
            int i = (int)a; i = i > 2047 ? 2047 : i;
            float f = a - (float)i;
            float l0 = lut[i], l1 = lut[i + 1];
            float qp = fmaf(f, l1 - l0, l0);
            float bp = bloom_exp(s[n] * cbl);
            float qv = qp * bp;
            q[n] = fmaxf(qv, 0.02f);
            qs += q[n];
        }
        float inv = frcp_(qs);
#pragma unroll
        for (int n = 0; n < 5; n++) {
            float wv = q[n] * inv;
            wout[off[n] + po] = wv;
            acc[n] += wv;
            s[n] -= hbB[n];
        }
    }

#pragma unroll
    for (int n = 0; n < 5; n++) {
        float v = acc[n];
#pragma unroll
        for (int o = 16; o; o >>= 1) v += __shfl_down_sync(0xffffffffu, v, o);
        if ((tid & 31) == 0) sred[tid >> 5][n] = v;
    }
    __syncthreads();
    if (tid < 5) {
        float t = 0.f;
#pragma unroll
        for (int wrp = 0; wrp < 8; wrp++) t += sred[wrp][tid];
        atomicAdd(&g_buf[OFF_WSUM + b * 5 + tid], t);
    }
}

// ---------------- K4: fused blur+downsample, ALU-lean (R11 rewrite) ----------------
// Output tile 64x8. Input tile 20 rows x 136 cols, float4-aligned (gxa = 2*ox0-4).
// Interior blocks: pure LDG.128, no bounds checks, no divisions anywhere.
template <bool APPLY_SCALE>
__global__ void k_down(const float* __restrict__ inL, const float* __restrict__ inW,
                       float* __restrict__ outL, float* __restrict__ outW,
                       int ih, int iw) {
    __shared__ float tile[20][136];
    __shared__ float hbuf[20][64];
    __shared__ float s_scale;
    int tid = threadIdx.x;
    int z = blockIdx.z;
    bool isW = (z >= NIMG);
    int img = isW ? z - NIMG : z;
    const float* in = isW ? inW : inL;
    float* out = isW ? outW : outL;
    int ox0 = blockIdx.x * 64, oy0 = blockIdx.y * 8;
    int ow = iw >> 1;
    const float* ip = in + (size_t)img * ih * iw;

    if (APPLY_SCALE) {
        if (tid == 0) s_scale = isW ? 1.0f : scale_for(img / 5, img % 5);
        __syncthreads();
    }
    float sc = APPLY_SCALE ? s_scale : 1.f;
    bool doScale = APPLY_SCALE && !isW;

    int gxa = 2 * ox0 - 4;          // 16B-aligned
    int gy0 = 2 * oy0 - 2;
    bool interior = (gxa >= 0) & (gxa + 136 <= iw) & (gy0 >= 0) & (gy0 + 20 <= ih);

    int lane = tid & 31, w = tid >> 5;

    if (interior) {
        // fast path: warp w loads rows {w, w+8, w+16}; 34 float4 per row.
#pragma unroll
        for (int rr0 = 0; rr0 < 24; rr0 += 8) {
            int rr = w + rr0;
            if (rr < 20) {
                const float4* rowp = (const float4*)(ip + (size_t)(gy0 + rr) * iw + gxa);
                float4* trow = (float4*)&tile[rr][0];
                for (int j = lane; j < 34; j += 32) {
                    float4 v = rowp[j];
                    if (doScale) {
                        v.x = fminf(fmaxf(v.x * sc, 0.f), 1.f);
                        v.y = fminf(fmaxf(v.y * sc, 0.f), 1.f);
                        v.z = fminf(fmaxf(v.z * sc, 0.f), 1.f);
                        v.w = fminf(fmaxf(v.w * sc, 0.f), 1.f);
                    }
                    trow[j] = v;
                }
            }
        }
    } else {
        // boundary path: per-element checks, zero padding.
#pragma unroll
        for (int rr0 = 0; rr0 < 24; rr0 += 8) {
            int rr = w + rr0;
            if (rr < 20) {
                int gy = gy0 + rr;
                bool rok = (gy >= 0) & (gy < ih);
                const float* rowp = ip + (size_t)(rok ? gy : 0) * iw;
                float4* trow = (float4*)&tile[rr][0];
                for (int j = lane; j < 34; j += 32) {
                    int gx = gxa + 4 * j;
                    float4 v;
                    v.x = (rok && gx + 0 >= 0 && gx + 0 < iw) ? rowp[gx + 0] : 0.f;
                    v.y = (rok && gx + 1 >= 0 && gx + 1 < iw) ? rowp[gx + 1] : 0.f;
                    v.z = (rok && gx + 2 >= 0 && gx + 2 < iw) ? rowp[gx + 2] : 0.f;
                    v.w = (rok && gx + 3 >= 0 && gx + 3 < iw) ? rowp[gx + 3] : 0.f;
                    if (doScale) {
                        v.x = fminf(fmaxf(v.x * sc, 0.f), 1.f);
                        v.y = fminf(fmaxf(v.y * sc, 0.f), 1.f);
                        v.z = fminf(fmaxf(v.z * sc, 0.f), 1.f);
                        v.w = fminf(fmaxf(v.w * sc, 0.f), 1.f);
                    }
                    trow[j] = v;
                }
            }
        }
    }
    __syncthreads();

    // horizontal 6-tap: 20 rows x 64 cols = 1280 = 5*256 exactly; shifts/masks only.
#pragma unroll
    for (int i = 0; i < 5; i++) {
        int id = tid + i * 256;
        int r = id >> 6, c = id & 63;
        int bc = 2 * c + 2;
        hbuf[r][c] = 0.03125f * (tile[r][bc] + tile[r][bc + 5])
                   + 0.15625f * (tile[r][bc + 1] + tile[r][bc + 4])
                   + 0.3125f  * (tile[r][bc + 2] + tile[r][bc + 3]);
    }
    __syncthreads();

    // vertical 6-tap: 8 rows x 64 cols = 512 = 2*256.
    size_t obase = (size_t)img * (ih >> 1) * ow;
#pragma unroll
    for (int i = 0; i < 2; i++) {
        int id = tid + i * 256;
        int c = id & 63, ty = id >> 6;   // ty in 0..7
        int rr = 2 * ty;
        float v = 0.03125f * (hbuf[rr][c] + hbuf[rr + 5][c])
                + 0.15625f * (hbuf[rr + 1][c] + hbuf[rr + 4][c])
                + 0.3125f  * (hbuf[rr + 2][c] + hbuf[rr + 3][c]);
        out[obase + (size_t)(oy0 + ty) * ow + (ox0 + c)] = v;
    }
}

// ---------------- K5: coarsest-level blend (pure gaussian level) ----------------
__global__ void k_blend4() {
    const float* gpL4 = g_buf + OFF_GPL + L4OFF;
    const float* gpW4 = g_buf + OFF_GPW + L4OFF;
    float* acc4 = g_buf + OFF_ACC + A4OFF;
    int idx = blockIdx.x * 256 + threadIdx.x;
    if (idx >= 4 * 4096) return;
    int b = idx >> 12, p = idx & 4095;
    float wv[5], s = 1e-6f;
#pragma unroll
    for (int n = 0; n < 5; n++) { wv[n] = gpW4[(b * 5 + n) * 4096 + p]; s += wv[n]; }
    float inv = frcp_(s);
    float o = 0.f;
#pragma unroll
    for (int n = 0; n < 5; n++) o += wv[n] * inv * gpL4[(b * 5 + n) * 4096 + p];
    acc4[idx] = o;
}

// ---------------- smem-patch bilinear helpers ----------------
#define PATCH(ip, r, c) patch[(ip) * 120 + (r) * 20 + (c)]

// ---------------- K6: mid-level blend + collapse (smem bilinear) ----------------
__global__ void k_blend(const float* __restrict__ Ll, const float* __restrict__ Ln,
                        const float* __restrict__ Wl, const float* __restrict__ accin,
                        float* __restrict__ accout, int oh, int ow) {
    __shared__ float patch[6 * 120];  // 5 Ln images + 1 acc
    int tid = threadIdx.x;
    int tx = tid & 31, ty = tid >> 5;
    int ox0 = blockIdx.x * 32, oy0 = blockIdx.y * 8;
    int b = blockIdx.z;
    int ih = oh >> 1, iw = ow >> 1;
    int sz = oh * ow, isz = ih * iw;
    int py0 = (oy0 >> 1) - 1, px0 = (ox0 >> 1) - 1;

    for (int idx = tid; idx < 6 * 108; idx += 256) {
        int ip = idx / 108, rem = idx - ip * 108;
        int r = rem / 18, c = rem - r * 18;
        int sy = py0 + r; sy = sy < 0 ? 0 : (sy > ih - 1 ? ih - 1 : sy);
        int sx = px0 + c; sx = sx < 0 ? 0 : (sx > iw - 1 ? iw - 1 : sx);
        const float* src = (ip < 5) ? (Ln + (b * 5 + ip) * isz) : (accin + b * isz);
        PATCH(ip, r, c) = src[sy * iw + sx];
    }
    __syncthreads();

    int x = ox0 + tx, y = oy0 + ty;
    int pix = y * ow + x;
    int ly = ((y - 1) >> 1) - py0, lx = ((x - 1) >> 1) - px0;
    float fy = (y & 1) ? 0.25f : 0.75f;
    float fx = (x & 1) ? 0.25f : 0.75f;
    float gy = 1.f - fy, gx = 1.f - fx;
    float w00 = gy * gx, w01 = gy * fx, w10 = fy * gx, w11 = fy * fx;

    float wv[5], ssum = 1e-6f;
#pragma unroll
    for (int n = 0; n < 5; n++) { wv[n] = Wl[(b * 5 + n) * sz + pix]; ssum += wv[n]; }
    float inv = frcp_(ssum);

    float s = w00 * PATCH(5, ly, lx)     + w01 * PATCH(5, ly, lx + 1)
            + w10 * PATCH(5, ly + 1, lx) + w11 * PATCH(5, ly + 1, lx + 1);
#pragma unroll
    for (int n = 0; n < 5; n++) {
        float lv = Ll[(b * 5 + n) * sz + pix];
        float up = w00 * PATCH(n, ly, lx)     + w01 * PATCH(n, ly, lx + 1)
                 + w10 * PATCH(n, ly + 1, lx) + w11 * PATCH(n, ly + 1, lx + 1);
        s += wv[n] * inv * (lv - up);
    }
    accout[b * sz + pix] = s;
}

// ---------------- K7: finest-level blend + collapse + clip -> output ----------------
__global__ void k_blend0(const float* __restrict__ Lin, const float* __restrict__ Wl,
                         float* __restrict__ out) {
    __shared__ float patch[6 * 120];
    __shared__ float s_sc[5];
    const float* gpL1 = g_buf + OFF_GPL + L1OFF;
    const float* accin = g_buf + OFF_ACC + A1OFF;
    int tid = threadIdx.x;
    int tx = tid & 31, ty = tid >> 5;
    int ox0 = blockIdx.x * 32, oy0 = blockIdx.y * 8;
    int b = blockIdx.z;
    const int ih = 512, iw = 512, isz = 262144;
    int py0 = (oy0 >> 1) - 1, px0 = (ox0 >> 1) - 1;

    if (tid < 5) s_sc[tid] = scale_for(b, tid);

    for (int idx = tid; idx < 6 * 108; idx += 256) {
        int ip = idx / 108, rem = idx - ip * 108;
        int r = rem / 18, c = rem - r * 18;
        int sy = py0 + r; sy = sy < 0 ? 0 : (sy > ih - 1 ? ih - 1 : sy);
        int sx = px0 + c; sx = sx < 0 ? 0 : (sx > iw - 1 ? iw - 1 : sx);
        const float* src = (ip < 5) ? (gpL1 + (b * 5 + ip) * isz) : (accin + b * isz);
        PATCH(ip, r, c) = src[sy * iw + sx];
    }
    __syncthreads();

    int x = ox0 + tx, y = oy0 + ty;
    int pix = y * W0 + x;
    int ly = ((y - 1) >> 1) - py0, lx = ((x - 1) >> 1) - px0;
    float fy = (y & 1) ? 0.25f : 0.75f;
    float fx = (x & 1) ? 0.25f : 0.75f;
    float gy = 1.f - fy, gx = 1.f - fx;
    float w00 = gy * gx, w01 = gy * fx, w10 = fy * gx, w11 = fy * fx;

    float wv[5], ssum = 1e-6f;
#pragma unroll
    for (int n = 0; n < 5; n++) { wv[n] = Wl[(b * 5 + n) * HW + pix]; ssum += wv[n]; }
    float inv = frcp_(ssum);

    float s = w00 * PATCH(5, ly, lx)     + w01 * PATCH(5, ly, lx + 1)
            + w10 * PATCH(5, ly + 1, lx) + w11 * PATCH(5, ly + 1, lx + 1);
#pragma unroll
    for (int n = 0; n < 5; n++) {
        float lv = Lin[(b * 5 + n) * HW + pix] * s_sc[n];
        lv = fminf(fmaxf(lv, 0.f), 1.f);
        float up = w00 * PATCH(n, ly, lx)     + w01 * PATCH(n, ly, lx + 1)
                 + w10 * PATCH(n, ly + 1, lx) + w11 * PATCH(n, ly + 1, lx + 1);
        s += wv[n] * inv * (lv - up);
    }
    out[b * HW + pix] = fminf(fmaxf(s, 0.f), 1.f);
}

// ---------------- host ----------------
extern "C" void kernel_launch(void* const* d_in, const int* in_sizes, int n_in,
                              void* d_out, int out_size) {
    const float* L = (const float*)d_in[0];
    float* out = (float*)d_out;

    float* base = nullptr;
    cudaGetSymbolAddress((void**)&base, g_buf);
    float* GPL = base + OFF_GPL;
    float* GPW = base + OFF_GPW;
    float* ACC = base + OFF_ACC;

    // output layout: [L_fused (4*HW)] ++ [w (20*HW)]
    float* wbuf = out + 4 * HW;

    k_zero<<<1, 64>>>();                       // idx 0
    k_hbox<<<NIMG * H0, 128>>>(L);             // idx 1
    k_qw<<<dim3(4, 32, B_), 256>>>(L, wbuf);   // idx 2
    // idx 3 <-- ncu capture slot: level-1 downsample (64x8 tiles, f4 fast path)
    k_down<true ><<<dim3(8, 64, 2 * NIMG), 256>>>(L,           wbuf,        GPL + L1OFF, GPW + L1OFF, 1024, 1024);
    k_down<false><<<dim3(4, 32, 2 * NIMG), 256>>>(GPL + L1OFF, GPW + L1OFF, GPL + L2OFF, GPW + L2OFF,  512,  512);
    k_down<false><<<dim3(2, 16, 2 * NIMG), 256>>>(GPL + L2OFF, GPW + L2OFF, GPL + L3OFF, GPW + L3OFF,  256,  256);
    k_down<false><<<dim3(1,  8, 2 * NIMG), 256>>>(GPL + L3OFF, GPW + L3OFF, GPL + L4OFF, GPW + L4OFF,  128,  128);

    k_blend4<<<64, 256>>>();
    k_blend<<<dim3( 4, 16, B_), 256>>>(GPL + L3OFF, GPL + L4OFF, GPW + L3OFF,
                                       ACC + A4OFF, ACC + A3OFF, 128, 128);
    k_blend<<<dim3( 8, 32, B_), 256>>>(GPL + L2OFF, GPL + L3OFF, GPW + L2OFF,
                                       ACC + A3OFF, ACC + A2OFF, 256, 256);
    k_blend<<<dim3(16, 64, B_), 256>>>(GPL + L1OFF, GPL + L2OFF, GPW + L1OFF,
                                       ACC + A2OFF, ACC + A1OFF, 512, 512);
    k_blend0<<<dim3(32, 128, B_), 256>>>(L, wbuf, out);
}